// round 6
// baseline (speedup 1.0000x reference)
#include <cuda_runtime.h>
#include <cstdint>
#include <math.h>

#define BB 16
#define NN 1024
#define DD 256
#define NH 8
#define DKH 32
#define ATTN_SCALE 0.17677669529663687f  // 1/sqrt(32)

// ---------------- scratch (static device globals; no allocation) ----------------
__device__ float g_Qp[BB*NN*DD];       // 16 MB
__device__ float g_Kp[BB*NN*DD];       // 16 MB
__device__ float g_qT[BB*DD*NN];       // 16 MB  (query transposed: [b][c][n])
__device__ float g_kg[BB*DD];
__device__ float g_kgpart[BB*8*DD];
__device__ float g_parth[BB*NH*NN];
__device__ float g_mu1[BB*DD*5];
__device__ float g_mu2[BB*DD*2];
__device__ float g_colpart[2][BB*4*5];
__device__ float g_mupart[2][BB*4*5*DD];
__device__ float g_P1[BB*NN*5];
__device__ float g_P2[BB*NN*2];

// ---------------- helpers ----------------
__device__ __forceinline__ float blockReduceSum256(float v, float* red) {
    #pragma unroll
    for (int off = 16; off; off >>= 1) v += __shfl_down_sync(0xffffffffu, v, off);
    int w = threadIdx.x >> 5;
    if ((threadIdx.x & 31) == 0) red[w] = v;
    __syncthreads();
    if (threadIdx.x < 32) {
        float r = (threadIdx.x < 8) ? red[threadIdx.x] : 0.f;
        #pragma unroll
        for (int off = 4; off; off >>= 1) r += __shfl_down_sync(0xffffffffu, r, off);
        if (threadIdx.x == 0) red[0] = r;
    }
    __syncthreads();
    float out = red[0];
    __syncthreads();
    return out;
}

__device__ __forceinline__ uint32_t f2tf32(float v) {
    uint32_t t;
    asm("cvt.rna.tf32.f32 %0, %1;" : "=r"(t) : "f"(v));
    return t;
}

__device__ __forceinline__ void mma_tf32(float& c0, float& c1, float& c2, float& c3,
                                         uint32_t a0, uint32_t a1, uint32_t a2, uint32_t a3,
                                         uint32_t b0, uint32_t b1) {
    asm("mma.sync.aligned.m16n8k8.row.col.f32.tf32.tf32.f32 "
        "{%0,%1,%2,%3}, {%4,%5,%6,%7}, {%8,%9}, {%0,%1,%2,%3};"
        : "+f"(c0), "+f"(c1), "+f"(c2), "+f"(c3)
        : "r"(a0), "r"(a1), "r"(a2), "r"(a3), "r"(b0), "r"(b1));
}

// ---------------- transpose: qT[b][c][n] = query[b][n][c] ----------------
__global__ __launch_bounds__(256) void transpose_kernel(const float* __restrict__ q,
                                                        float* __restrict__ qT) {
    __shared__ float tile[32][33];
    const int b = blockIdx.z;
    const int n0 = blockIdx.x * 32;
    const int c0 = blockIdx.y * 32;
    const int tx = threadIdx.x, ty = threadIdx.y;
    #pragma unroll
    for (int j = 0; j < 4; j++)
        tile[ty + 8*j][tx] = q[(size_t)(b*NN + n0 + ty + 8*j) * DD + c0 + tx];
    __syncthreads();
    #pragma unroll
    for (int j = 0; j < 4; j++)
        qT[(size_t)(b*DD + c0 + ty + 8*j) * NN + n0 + tx] = tile[tx][ty + 8*j];
}

// ---------------- TF32 projection GEMM: C[16384,256] = A @ W^T + bias ----------------
// block tile 128(m) x 128(n), k-tile 32; 8 warps as 4(m) x 2(n); warp tile 32x64
__global__ __launch_bounds__(256) void proj_tf32_kernel(const float* __restrict__ A,
                                                        const float* __restrict__ W,
                                                        const float* __restrict__ bias,
                                                        float* __restrict__ C) {
    __shared__ uint32_t As[128][36];
    __shared__ uint32_t Ws[128][36];
    const int bm = blockIdx.y * 128;
    const int bn = blockIdx.x * 128;
    const int tid = threadIdx.x;
    const int wid = tid >> 5, lane = tid & 31;
    const int wm = wid & 3, wn = wid >> 2;
    const int gid = lane >> 2, tig = lane & 3;

    float acc[2][8][4];
    #pragma unroll
    for (int mt = 0; mt < 2; mt++)
        #pragma unroll
        for (int nt = 0; nt < 8; nt++)
            #pragma unroll
            for (int i = 0; i < 4; i++) acc[mt][nt][i] = 0.f;

    for (int k0 = 0; k0 < 256; k0 += 32) {
        __syncthreads();
        #pragma unroll
        for (int i = tid; i < 128*32; i += 256) {
            int r = i >> 5, c = i & 31;
            As[r][c] = f2tf32(A[(size_t)(bm + r) * 256 + k0 + c]);
            Ws[r][c] = f2tf32(W[(size_t)(bn + r) * 256 + k0 + c]);
        }
        __syncthreads();
        #pragma unroll
        for (int ks = 0; ks < 4; ks++) {
            uint32_t af[2][4];
            #pragma unroll
            for (int mt = 0; mt < 2; mt++) {
                int r = wm*32 + mt*16 + gid;
                int c = ks*8 + tig;
                af[mt][0] = As[r][c];     af[mt][1] = As[r+8][c];
                af[mt][2] = As[r][c+4];   af[mt][3] = As[r+8][c+4];
            }
            #pragma unroll
            for (int nt = 0; nt < 8; nt++) {
                int nr = wn*64 + nt*8 + gid;
                uint32_t b0 = Ws[nr][ks*8 + tig];
                uint32_t b1 = Ws[nr][ks*8 + tig + 4];
                #pragma unroll
                for (int mt = 0; mt < 2; mt++)
                    mma_tf32(acc[mt][nt][0], acc[mt][nt][1], acc[mt][nt][2], acc[mt][nt][3],
                             af[mt][0], af[mt][1], af[mt][2], af[mt][3], b0, b1);
            }
        }
    }
    #pragma unroll
    for (int mt = 0; mt < 2; mt++) {
        int r = bm + wm*32 + mt*16 + gid;
        #pragma unroll
        for (int nt = 0; nt < 8; nt++) {
            int col = bn + wn*64 + nt*8 + 2*tig;
            float bv0 = bias[col], bv1 = bias[col + 1];
            float2 v0 = make_float2(acc[mt][nt][0] + bv0, acc[mt][nt][1] + bv1);
            float2 v1 = make_float2(acc[mt][nt][2] + bv0, acc[mt][nt][3] + bv1);
            *(float2*)&C[(size_t)r * 256 + col] = v0;
            *(float2*)&C[(size_t)(r + 8) * 256 + col] = v1;
        }
    }
}

// ---------------- key_global partials ----------------
__global__ __launch_bounds__(256) void kg_partial_kernel(const float* __restrict__ Kp,
                                                         const float* __restrict__ value,
                                                         float* __restrict__ kgpart) {
    __shared__ float vs[128];
    const int chunk = blockIdx.x, b = blockIdx.y;
    const int c = threadIdx.x;
    const int n0 = chunk * 128;
    if (c < 128) vs[c] = value[b*NN + n0 + c];
    __syncthreads();
    const float* kp = &Kp[(size_t)(b*NN + n0) * DD + c];
    float a0 = 0.f, a1 = 0.f, a2 = 0.f, a3 = 0.f;
    #pragma unroll 4
    for (int n = 0; n < 128; n += 4) {
        a0 += kp[(size_t)(n+0) * DD] * vs[n+0];
        a1 += kp[(size_t)(n+1) * DD] * vs[n+1];
        a2 += kp[(size_t)(n+2) * DD] * vs[n+2];
        a3 += kp[(size_t)(n+3) * DD] * vs[n+3];
    }
    kgpart[(size_t)(b*8 + chunk) * DD + c] = (a0 + a1) + (a2 + a3);
}

__global__ __launch_bounds__(256) void kg_finalize_kernel(const float* __restrict__ kgpart,
                                                          float* __restrict__ kg) {
    const int b = blockIdx.x, c = threadIdx.x;
    float s = 0.f;
    #pragma unroll
    for (int ch = 0; ch < 8; ch++) s += kgpart[(size_t)(b*8 + ch) * DD + c];
    kg[b*DD + c] = s * (1.0f / NN);
}

// ---------------- TF32 flash attention with scalar V ----------------
// block: 128 queries for one (b,h); 8 warps = 4(m:32q) x 2(n:64keys); key tiles of 128
__global__ __launch_bounds__(256) void flash_mma_kernel(const float* __restrict__ Qp,
                                                        const float* __restrict__ Kp,
                                                        const float* __restrict__ value,
                                                        float* __restrict__ parth) {
    __shared__ uint32_t Qs[128][36];
    __shared__ uint32_t Ks[128][36];
    __shared__ float vs[128];
    __shared__ float lred[2][128];
    __shared__ float sred[2][128];
    const int b = blockIdx.z, h = blockIdx.y;
    const int q0 = blockIdx.x * 128;
    const int tid = threadIdx.x;
    const int wid = tid >> 5, lane = tid & 31;
    const int wm = wid & 3, wn = wid >> 2;
    const int gid = lane >> 2, tig = lane & 3;

    // load Q tile (128 x 32), tf32
    {
        const float* src = &Qp[(size_t)(b*NN + q0) * DD + h * DKH];
        #pragma unroll
        for (int i = tid; i < 128*32; i += 256) {
            int r = i >> 5, c = i & 31;
            Qs[r][c] = f2tf32(src[(size_t)r * DD + c]);
        }
    }
    __syncthreads();

    // persistent A fragments: 2 m-tiles x 4 k-subs x 4 regs
    uint32_t afr[2][4][4];
    #pragma unroll
    for (int mt = 0; mt < 2; mt++)
        #pragma unroll
        for (int ks = 0; ks < 4; ks++) {
            int r = wm*32 + mt*16 + gid;
            int c = ks*8 + tig;
            afr[mt][ks][0] = Qs[r][c];     afr[mt][ks][1] = Qs[r+8][c];
            afr[mt][ks][2] = Qs[r][c+4];   afr[mt][ks][3] = Qs[r+8][c+4];
        }

    float la[2][2] = {{0.f,0.f},{0.f,0.f}};
    float sa[2][2] = {{0.f,0.f},{0.f,0.f}};

    for (int kt = 0; kt < NN; kt += 128) {
        __syncthreads();
        const float* ksrc = &Kp[(size_t)(b*NN + kt) * DD + h * DKH];
        #pragma unroll
        for (int i = tid; i < 128*32; i += 256) {
            int r = i >> 5, c = i & 31;
            Ks[r][c] = f2tf32(ksrc[(size_t)r * DD + c]);
        }
        if (tid < 128) vs[tid] = value[b*NN + kt + tid];
        __syncthreads();

        #pragma unroll
        for (int nt = 0; nt < 8; nt++) {
            int nb = wn*64 + nt*8;
            uint32_t bfr[4][2];
            #pragma unroll
            for (int ks = 0; ks < 4; ks++) {
                bfr[ks][0] = Ks[nb + gid][ks*8 + tig];
                bfr[ks][1] = Ks[nb + gid][ks*8 + tig + 4];
            }
            float v0 = vs[nb + 2*tig], v1 = vs[nb + 2*tig + 1];
            #pragma unroll
            for (int mt = 0; mt < 2; mt++) {
                float c0 = 0.f, c1 = 0.f, c2 = 0.f, c3 = 0.f;
                #pragma unroll
                for (int ks = 0; ks < 4; ks++)
                    mma_tf32(c0, c1, c2, c3,
                             afr[mt][ks][0], afr[mt][ks][1], afr[mt][ks][2], afr[mt][ks][3],
                             bfr[ks][0], bfr[ks][1]);
                float e0 = __expf(c0 * ATTN_SCALE);
                float e1 = __expf(c1 * ATTN_SCALE);
                float e2 = __expf(c2 * ATTN_SCALE);
                float e3 = __expf(c3 * ATTN_SCALE);
                la[mt][0] += e0 + e1;  sa[mt][0] += e0*v0 + e1*v1;
                la[mt][1] += e2 + e3;  sa[mt][1] += e2*v0 + e3*v1;
            }
        }
    }

    // reduce across the 4 lanes of each quad (they share the same q row)
    #pragma unroll
    for (int mt = 0; mt < 2; mt++)
        #pragma unroll
        for (int rr = 0; rr < 2; rr++) {
            float l = la[mt][rr], s = sa[mt][rr];
            l += __shfl_xor_sync(0xffffffffu, l, 1);
            l += __shfl_xor_sync(0xffffffffu, l, 2);
            s += __shfl_xor_sync(0xffffffffu, s, 1);
            s += __shfl_xor_sync(0xffffffffu, s, 2);
            la[mt][rr] = l; sa[mt][rr] = s;
        }
    if (tig == 0) {
        #pragma unroll
        for (int mt = 0; mt < 2; mt++) {
            int r0 = wm*32 + mt*16 + gid;
            lred[wn][r0]     = la[mt][0];  sred[wn][r0]     = sa[mt][0];
            lred[wn][r0 + 8] = la[mt][1];  sred[wn][r0 + 8] = sa[mt][1];
        }
    }
    __syncthreads();
    if (tid < 128) {
        float l = lred[0][tid] + lred[1][tid];
        float s = sred[0][tid] + sred[1][tid];
        parth[(size_t)(b*NH + h) * NN + q0 + tid] = s / l;
    }
}

// ---------------- combine: f = (1-lam)*part + lam*whole -> out[:, :, 0] ----------------
__global__ __launch_bounds__(256) void combine_kernel(const float* __restrict__ Qp,
                                                      const float* __restrict__ kg,
                                                      const float* __restrict__ parth,
                                                      const float* __restrict__ lamda,
                                                      float* __restrict__ out) {
    int idx = blockIdx.x * 256 + threadIdx.x;   // b*1024+n
    int b = idx >> 10, n = idx & 1023;
    const float4* q   = (const float4*)&Qp[(size_t)idx * DD];
    const float4* kgp = (const float4*)&kg[b * DD];
    float wsum = 0.f;
    #pragma unroll
    for (int h = 0; h < NH; h++) {
        float d = 0.f;
        #pragma unroll
        for (int i = 0; i < 8; i++) {
            float4 qv = q[h*8 + i], kv = kgp[h*8 + i];
            d += qv.x*kv.x + qv.y*kv.y + qv.z*kv.z + qv.w*kv.w;
        }
        wsum += fmaxf(d * ATTN_SCALE, 0.f);
    }
    float whole = wsum * 0.125f;
    float p = 0.f;
    #pragma unroll
    for (int h = 0; h < NH; h++) p += parth[(size_t)(b*NH + h) * NN + n];
    p *= 0.125f;
    float lam = lamda[0];
    out[(size_t)idx * 8] = (1.f - lam) * p + lam * whole;
}

// ---------------- fused PMMS-1 iteration ----------------
__global__ __launch_bounds__(256) void pmms1_iter_kernel(const float* __restrict__ qT,
                                                         const float* __restrict__ query,
                                                         const float* __restrict__ mu_a,
                                                         const float* __restrict__ mupart_in,
                                                         const float* __restrict__ colpart_in,
                                                         float* __restrict__ mupart_out,
                                                         float* __restrict__ colpart_out,
                                                         int first) {
    __shared__ float mus2[256][8];
    __shared__ float zz2[256][8];
    __shared__ float red[8];
    const int chunk = blockIdx.x, b = blockIdx.y;
    const int tid = threadIdx.x;

    if (first) {
        for (int i = tid; i < 256 * 5; i += 256) mus2[i / 5][i % 5] = mu_a[i];
        __syncthreads();
    } else {
        const int c = tid;
        float v[5];
        #pragma unroll
        for (int k = 0; k < 5; k++) {
            float cs = 0.f, a = 0.f;
            #pragma unroll
            for (int ch = 0; ch < 4; ch++) {
                cs += colpart_in[(b*4 + ch) * 5 + k];
                a  += mupart_in[(size_t)((b*4 + ch) * 5 + k) * 256 + c];
            }
            v[k] = a / (1e-6f + cs);
        }
        #pragma unroll
        for (int k = 0; k < 5; k++) {
            float s = blockReduceSum256(v[k] * v[k], red);
            mus2[c][k] = v[k] / (1e-6f + sqrtf(s));
        }
        __syncthreads();
    }

    {
        const int n = chunk * 256 + tid;
        const float* qp = &qT[(size_t)(b*DD) * NN + n];
        float acc[5] = {0.f, 0.f, 0.f, 0.f, 0.f};
        #pragma unroll 4
        for (int c = 0; c < 256; c++) {
            float qv = qp[(size_t)c * NN];
            float4 m4 = *(const float4*)&mus2[c][0];
            float m5 = mus2[c][4];
            acc[0] += qv * m4.x; acc[1] += qv * m4.y; acc[2] += qv * m4.z;
            acc[3] += qv * m4.w; acc[4] += qv * m5;
        }
        float m = acc[0];
        #pragma unroll
        for (int k = 1; k < 5; k++) m = fmaxf(m, acc[k]);
        float sum = 0.f;
        #pragma unroll
        for (int k = 0; k < 5; k++) { acc[k] = __expf(20.f * (acc[k] - m)); sum += acc[k]; }
        float inv = 1.f / sum;
        #pragma unroll
        for (int k = 0; k < 5; k++) {
            acc[k] *= inv;
            zz2[tid][k] = acc[k];
        }
        #pragma unroll
        for (int k = 0; k < 5; k++) {
            float s = blockReduceSum256(acc[k], red);
            if (tid == 0) colpart_out[(b*4 + chunk) * 5 + k] = s;
        }
    }
    __syncthreads();

    {
        const int c = tid;
        const float* qb = &query[(size_t)(b*NN + chunk*256) * DD + c];
        float acc[5] = {0.f, 0.f, 0.f, 0.f, 0.f};
        #pragma unroll 4
        for (int n = 0; n < 256; n++) {
            float qv = qb[(size_t)n * DD];
            float4 z4 = *(const float4*)&zz2[n][0];
            float z5 = zz2[n][4];
            acc[0] += qv * z4.x; acc[1] += qv * z4.y; acc[2] += qv * z4.z;
            acc[3] += qv * z4.w; acc[4] += qv * z5;
        }
        #pragma unroll
        for (int k = 0; k < 5; k++)
            mupart_out[(size_t)((b*4 + chunk) * 5 + k) * 256 + c] = acc[k];
    }
}

// ---------------- PMMS mu finalize ----------------
template<int K>
__global__ __launch_bounds__(256) void mustep_finalize(const float* __restrict__ mupart,
                                                       const float* __restrict__ colpart,
                                                       float* __restrict__ mu) {
    __shared__ float red[8];
    const int b = blockIdx.x, c = threadIdx.x;
    float acc[K];
    #pragma unroll
    for (int k = 0; k < K; k++) {
        float cs = 0.f, a = 0.f;
        #pragma unroll
        for (int ch = 0; ch < 4; ch++) {
            cs += colpart[(b*4 + ch) * K + k];
            a  += mupart[(size_t)((b*4 + ch) * K + k) * 256 + c];
        }
        acc[k] = a / (1e-6f + cs);
    }
    #pragma unroll
    for (int k = 0; k < K; k++) {
        float s = blockReduceSum256(acc[k] * acc[k], red);
        acc[k] = acc[k] / (1e-6f + sqrtf(s));
    }
    #pragma unroll
    for (int k = 0; k < K; k++) mu[(b*256 + c) * K + k] = acc[k];
}

// ---------------- P = softmax(query @ mu) via qT ----------------
template<int K>
__global__ __launch_bounds__(256) void zstepT_kernel(const float* __restrict__ qT,
                                                     const float* __restrict__ mu,
                                                     float* __restrict__ P) {
    __shared__ float mus2[256][8];
    const int b = blockIdx.y, tid = threadIdx.x;
    for (int i = tid; i < 256 * K; i += 256) mus2[i / K][i % K] = mu[(b*256) * K + i];
    __syncthreads();
    const int n = blockIdx.x * 256 + tid;
    const float* qp = &qT[(size_t)(b*DD) * NN + n];
    float acc[K];
    #pragma unroll
    for (int k = 0; k < K; k++) acc[k] = 0.f;
    #pragma unroll 4
    for (int c = 0; c < 256; c++) {
        float qv = qp[(size_t)c * NN];
        #pragma unroll
        for (int k = 0; k < K; k++) acc[k] += qv * mus2[c][k];
    }
    float m = acc[0];
    #pragma unroll
    for (int k = 1; k < K; k++) m = fmaxf(m, acc[k]);
    float sum = 0.f;
    #pragma unroll
    for (int k = 0; k < K; k++) { acc[k] = __expf(acc[k] - m); sum += acc[k]; }
    float inv = 1.f / sum;
    #pragma unroll
    for (int k = 0; k < K; k++) P[(size_t)(b*NN + n) * K + k] = acc[k] * inv;
}

// ---------------- PMMS-2 ----------------
__global__ __launch_bounds__(256) void pmms2_kernel(const float* __restrict__ mu1,
                                                    const float* __restrict__ mu_b,
                                                    float* __restrict__ mu2) {
    const int b = blockIdx.x, c = threadIdx.x;
    __shared__ float node[256][5];
    __shared__ float zsh[5][2];
    __shared__ float Ssh[10];
    __shared__ float red[8];
    #pragma unroll
    for (int n = 0; n < 5; n++) node[c][n] = mu1[(b*256 + c) * 5 + n];
    float mk0 = mu_b[c*2 + 0], mk1 = mu_b[c*2 + 1];

    for (int it = 0; it < 10; it++) {
        #pragma unroll
        for (int j = 0; j < 10; j++) {
            int n = j >> 1, k = j & 1;
            float v = node[c][n] * (k ? mk1 : mk0);
            float s = blockReduceSum256(v, red);
            if (c == 0) Ssh[j] = s;
        }
        __syncthreads();
        if (c == 0) {
            float csum0 = 0.f, csum1 = 0.f;
            float zt[5][2];
            #pragma unroll
            for (int n = 0; n < 5; n++) {
                float a = 20.f * Ssh[n*2 + 0];
                float q = 20.f * Ssh[n*2 + 1];
                float m = fmaxf(a, q);
                float ea = __expf(a - m), eb = __expf(q - m);
                float inv = 1.f / (ea + eb);
                zt[n][0] = ea * inv; zt[n][1] = eb * inv;
                csum0 += zt[n][0];   csum1 += zt[n][1];
            }
            #pragma unroll
            for (int n = 0; n < 5; n++) {
                zsh[n][0] = zt[n][0] / (1e-6f + csum0);
                zsh[n][1] = zt[n][1] / (1e-6f + csum1);
            }
        }
        __syncthreads();
        float nk0 = 0.f, nk1 = 0.f;
        #pragma unroll
        for (int n = 0; n < 5; n++) {
            nk0 += node[c][n] * zsh[n][0];
            nk1 += node[c][n] * zsh[n][1];
        }
        float s0 = blockReduceSum256(nk0 * nk0, red);
        float s1 = blockReduceSum256(nk1 * nk1, red);
        mk0 = nk0 / (1e-6f + sqrtf(s0));
        mk1 = nk1 / (1e-6f + sqrtf(s1));
        __syncthreads();
    }
    mu2[(b*256 + c) * 2 + 0] = mk0;
    mu2[(b*256 + c) * 2 + 1] = mk1;
}

// ---------------- node_weight ----------------
__global__ __launch_bounds__(1024) void nw_kernel(const float* __restrict__ P, int CH,
                                                  const float* __restrict__ w1,
                                                  const float* __restrict__ b1,
                                                  const float* __restrict__ g,
                                                  const float* __restrict__ be,
                                                  const float* __restrict__ w2,
                                                  const float* __restrict__ b2,
                                                  float* __restrict__ out, int outOff) {
    __shared__ float img[34][34];
    __shared__ float t1[8][34][34];
    __shared__ float sw1[144], sw2[144], sb1[16], sg[16], sbe[16];
    const int blk = blockIdx.x;
    const int b = blk / CH, ch = blk % CH;
    const int t = threadIdx.x;
    const int r = t >> 5, c = t & 31;

    for (int i = t; i < 34*34; i += 1024) ((float*)img)[i] = 0.f;
    for (int i = t; i < 8*34*34; i += 1024) ((float*)t1)[i] = 0.f;
    const float bninv = rsqrtf(1.f + 1e-5f);
    if (t < 144) { sw1[t] = w1[t]; sw2[t] = w2[t]; }
    if (t < 16)  { sb1[t] = b1[t]; sg[t] = g[t] * bninv; sbe[t] = be[t]; }
    __syncthreads();

    const int n = r * 32 + c;
    float xv = P[(size_t)((b << 10) + n) * CH + ch];
    img[r + 1][c + 1] = xv;
    float acc = b2[0];

    for (int half = 0; half < 2; half++) {
        __syncthreads();
        #pragma unroll
        for (int oc = 0; oc < 8; oc++) {
            int o = half * 8 + oc;
            float v = sb1[o];
            #pragma unroll
            for (int dy = 0; dy < 3; dy++)
                #pragma unroll
                for (int dx = 0; dx < 3; dx++)
                    v += sw1[o*9 + dy*3 + dx] * img[r + dy][c + dx];
            v = fmaxf(v * sg[o] + sbe[o], 0.f);
            t1[oc][r + 1][c + 1] = v;
        }
        __syncthreads();
        #pragma unroll
        for (int ic = 0; ic < 8; ic++) {
            int i2 = half * 8 + ic;
            #pragma unroll
            for (int dy = 0; dy < 3; dy++)
                #pragma unroll
                for (int dx = 0; dx < 3; dx++)
                    acc += sw2[i2*9 + dy*3 + dx] * t1[ic][r + dy][c + dx];
        }
    }
    float y = 1.f / (1.f + __expf(-acc));
    out[(size_t)((b << 10) + n) * 8 + outOff + ch] = xv * y;
}

// ---------------- launch ----------------
extern "C" void kernel_launch(void* const* d_in, const int* in_sizes, int n_in,
                              void* d_out, int out_size) {
    const float* query = (const float*)d_in[0];
    const float* key   = (const float*)d_in[1];
    const float* value = (const float*)d_in[2];
    const float* lamda = (const float*)d_in[3];
    const float* W0    = (const float*)d_in[4];
    const float* b0    = (const float*)d_in[5];
    const float* W1    = (const float*)d_in[6];
    const float* b1    = (const float*)d_in[7];
    const float* mu_a  = (const float*)d_in[8];
    const float* mu_b  = (const float*)d_in[9];
    const float* nw1_w1 = (const float*)d_in[10];
    const float* nw1_b1 = (const float*)d_in[11];
    const float* nw1_g  = (const float*)d_in[12];
    const float* nw1_be = (const float*)d_in[13];
    const float* nw1_w2 = (const float*)d_in[14];
    const float* nw1_b2 = (const float*)d_in[15];
    const float* nw2_w1 = (const float*)d_in[16];
    const float* nw2_b1 = (const float*)d_in[17];
    const float* nw2_g  = (const float*)d_in[18];
    const float* nw2_be = (const float*)d_in[19];
    const float* nw2_w2 = (const float*)d_in[20];
    const float* nw2_b2 = (const float*)d_in[21];
    float* out = (float*)d_out;

    float *Qp, *Kp, *qT, *kg, *kgpart, *parth, *mu1, *mu2, *P1, *P2;
    float *colpart, *mupart;
    cudaGetSymbolAddress((void**)&Qp, g_Qp);
    cudaGetSymbolAddress((void**)&Kp, g_Kp);
    cudaGetSymbolAddress((void**)&qT, g_qT);
    cudaGetSymbolAddress((void**)&kg, g_kg);
    cudaGetSymbolAddress((void**)&kgpart, g_kgpart);
    cudaGetSymbolAddress((void**)&parth, g_parth);
    cudaGetSymbolAddress((void**)&mu1, g_mu1);
    cudaGetSymbolAddress((void**)&mu2, g_mu2);
    cudaGetSymbolAddress((void**)&colpart, g_colpart);
    cudaGetSymbolAddress((void**)&mupart, g_mupart);
    cudaGetSymbolAddress((void**)&P1, g_P1);
    cudaGetSymbolAddress((void**)&P2, g_P2);

    float* mp[2] = {mupart, mupart + BB*4*5*DD};
    float* cp[2] = {colpart, colpart + BB*4*5};

    // Transpose query for coalesced PMMS access
    transpose_kernel<<<dim3(32, 8, 16), dim3(32, 8)>>>(query, qT);

    // Projections (TF32 tensor cores)
    proj_tf32_kernel<<<dim3(2, 128), 256>>>(query, W0, b0, Qp);
    proj_tf32_kernel<<<dim3(2, 128), 256>>>(key,   W1, b1, Kp);

    // Attention
    kg_partial_kernel<<<dim3(8, BB), 256>>>(Kp, value, kgpart);
    kg_finalize_kernel<<<BB, 256>>>(kgpart, kg);
    flash_mma_kernel<<<dim3(8, NH, BB), 256>>>(Qp, Kp, value, parth);
    combine_kernel<<<64, 256>>>(Qp, kg, parth, lamda, out);

    // PMMS-1 (K=5, 10 fused iterations, ping-pong partials)
    for (int it = 0; it < 10; it++) {
        int ob = it & 1;
        int ib = ob ^ 1;
        pmms1_iter_kernel<<<dim3(4, BB), 256>>>(qT, query, mu_a,
                                                mp[ib], cp[ib], mp[ob], cp[ob],
                                                it == 0 ? 1 : 0);
    }
    mustep_finalize<5><<<BB, 256>>>(mp[1], cp[1], mu1);

    // P1 = softmax(query @ mu1)
    zstepT_kernel<5><<<dim3(4, BB), 256>>>(qT, mu1, P1);

    // PMMS-2 (node = mu1, K=2)
    pmms2_kernel<<<BB, 256>>>(mu1, mu_b, mu2);
    zstepT_kernel<2><<<dim3(4, BB), 256>>>(qT, mu2, P2);

    // node_weight gating
    nw_kernel<<<BB * 5, 1024>>>(P1, 5, nw1_w1, nw1_b1, nw1_g, nw1_be, nw1_w2, nw1_b2, out, 1);
    nw_kernel<<<BB * 2, 1024>>>(P2, 2, nw2_w1, nw2_b1, nw2_g, nw2_be, nw2_w2, nw2_b2, out, 6);
}

// round 10
// speedup vs baseline: 1.3230x; 1.3230x over previous
#include <cuda_runtime.h>
#include <cstdint>
#include <math.h>

#define BB 16
#define NN 1024
#define DD 256
#define NH 8
#define DKH 32
#define NCH 8     // PMMS chunks per batch
#define CHT 128   // tokens per chunk
#define ATTN_SCALE 0.17677669529663687f  // 1/sqrt(32)

// ---------------- scratch (static device globals; no allocation) ----------------
__device__ float g_Qp[BB*NN*DD];       // 16 MB
__device__ float g_Kp[BB*NN*DD];       // 16 MB
__device__ float g_qT[BB*DD*NN];       // 16 MB  (query transposed: [b][c][n])
__device__ float g_kg[BB*DD];
__device__ float g_kgpart[BB*8*DD];
__device__ float g_parth[BB*NH*NN];
__device__ float g_mu1[BB*DD*5];
__device__ float g_mu2[BB*DD*2];
__device__ float g_colpart[2][BB*NCH*5];
__device__ float g_mupart[2][BB*NCH*5*DD];
__device__ float g_P1[BB*NN*5];
__device__ float g_P2[BB*NN*2];

// ---------------- helpers ----------------
__device__ __forceinline__ float blockReduceSum256(float v, float* red) {
    #pragma unroll
    for (int off = 16; off; off >>= 1) v += __shfl_down_sync(0xffffffffu, v, off);
    int w = threadIdx.x >> 5;
    if ((threadIdx.x & 31) == 0) red[w] = v;
    __syncthreads();
    if (threadIdx.x < 32) {
        float r = (threadIdx.x < 8) ? red[threadIdx.x] : 0.f;
        #pragma unroll
        for (int off = 4; off; off >>= 1) r += __shfl_down_sync(0xffffffffu, r, off);
        if (threadIdx.x == 0) red[0] = r;
    }
    __syncthreads();
    float out = red[0];
    __syncthreads();
    return out;
}

// ---------------- transpose: qT[b][c][n] = query[b][n][c] ----------------
__global__ __launch_bounds__(256) void transpose_kernel(const float* __restrict__ q,
                                                        float* __restrict__ qT) {
    __shared__ float tile[32][33];
    const int b = blockIdx.z;
    const int n0 = blockIdx.x * 32;
    const int c0 = blockIdx.y * 32;
    const int tx = threadIdx.x, ty = threadIdx.y;
    #pragma unroll
    for (int j = 0; j < 4; j++)
        tile[ty + 8*j][tx] = q[(size_t)(b*NN + n0 + ty + 8*j) * DD + c0 + tx];
    __syncthreads();
    #pragma unroll
    for (int j = 0; j < 4; j++)
        qT[(size_t)(b*DD + c0 + ty + 8*j) * NN + n0 + tx] = tile[tx][ty + 8*j];
}

// ---------------- projection GEMM: C[16384,256] = A[16384,256] @ W^T + bias ----------------
__global__ __launch_bounds__(256) void proj_kernel(const float* __restrict__ A,
                                                   const float* __restrict__ W,
                                                   const float* __restrict__ bias,
                                                   float* __restrict__ C) {
    __shared__ float As[8][132];
    __shared__ float Bs[8][132];
    const int bm = blockIdx.y * 128;
    const int bn = blockIdx.x * 128;
    const int t  = threadIdx.x;
    const int tx = t & 15, ty = t >> 4;
    const int tn0 = tx * 8, tm0 = ty * 8;
    const int lrow = t >> 1, lk = (t & 1) * 4;

    float acc[8][8];
    #pragma unroll
    for (int i = 0; i < 8; i++)
        #pragma unroll
        for (int j = 0; j < 8; j++) acc[i][j] = 0.f;

    for (int k0 = 0; k0 < 256; k0 += 8) {
        float4 a = *(const float4*)&A[(size_t)(bm + lrow) * 256 + k0 + lk];
        float4 w = *(const float4*)&W[(size_t)(bn + lrow) * 256 + k0 + lk];
        As[lk+0][lrow] = a.x; As[lk+1][lrow] = a.y; As[lk+2][lrow] = a.z; As[lk+3][lrow] = a.w;
        Bs[lk+0][lrow] = w.x; Bs[lk+1][lrow] = w.y; Bs[lk+2][lrow] = w.z; Bs[lk+3][lrow] = w.w;
        __syncthreads();
        #pragma unroll
        for (int k = 0; k < 8; k++) {
            float4 ra0 = *(const float4*)&As[k][tm0];
            float4 ra1 = *(const float4*)&As[k][tm0 + 4];
            float4 rb0 = *(const float4*)&Bs[k][tn0];
            float4 rb1 = *(const float4*)&Bs[k][tn0 + 4];
            float ra[8] = {ra0.x, ra0.y, ra0.z, ra0.w, ra1.x, ra1.y, ra1.z, ra1.w};
            float rb[8] = {rb0.x, rb0.y, rb0.z, rb0.w, rb1.x, rb1.y, rb1.z, rb1.w};
            #pragma unroll
            for (int i = 0; i < 8; i++)
                #pragma unroll
                for (int j = 0; j < 8; j++) acc[i][j] += ra[i] * rb[j];
        }
        __syncthreads();
    }
    #pragma unroll
    for (int i = 0; i < 8; i++) {
        #pragma unroll
        for (int j = 0; j < 8; j++) acc[i][j] += bias[bn + tn0 + j];
        float4* dst = (float4*)&C[(size_t)(bm + tm0 + i) * 256 + bn + tn0];
        dst[0] = make_float4(acc[i][0], acc[i][1], acc[i][2], acc[i][3]);
        dst[1] = make_float4(acc[i][4], acc[i][5], acc[i][6], acc[i][7]);
    }
}

// ---------------- key_global partials ----------------
__global__ __launch_bounds__(256) void kg_partial_kernel(const float* __restrict__ Kp,
                                                         const float* __restrict__ value,
                                                         float* __restrict__ kgpart) {
    __shared__ float vs[128];
    const int chunk = blockIdx.x, b = blockIdx.y;
    const int c = threadIdx.x;
    const int n0 = chunk * 128;
    if (c < 128) vs[c] = value[b*NN + n0 + c];
    __syncthreads();
    const float* kp = &Kp[(size_t)(b*NN + n0) * DD + c];
    float a0 = 0.f, a1 = 0.f, a2 = 0.f, a3 = 0.f;
    #pragma unroll 4
    for (int n = 0; n < 128; n += 4) {
        a0 += kp[(size_t)(n+0) * DD] * vs[n+0];
        a1 += kp[(size_t)(n+1) * DD] * vs[n+1];
        a2 += kp[(size_t)(n+2) * DD] * vs[n+2];
        a3 += kp[(size_t)(n+3) * DD] * vs[n+3];
    }
    kgpart[(size_t)(b*8 + chunk) * DD + c] = (a0 + a1) + (a2 + a3);
}

__global__ __launch_bounds__(256) void kg_finalize_kernel(const float* __restrict__ kgpart,
                                                          float* __restrict__ kg) {
    const int b = blockIdx.x, c = threadIdx.x;
    float s = 0.f;
    #pragma unroll
    for (int ch = 0; ch < 8; ch++) s += kgpart[(size_t)(b*8 + ch) * DD + c];
    kg[b*DD + c] = s * (1.0f / NN);
}

// ---------------- flash attention with scalar V; 2 queries per thread ----------------
__global__ __launch_bounds__(128) void flash_kernel(const float* __restrict__ Qp,
                                                    const float* __restrict__ Kp,
                                                    const float* __restrict__ value,
                                                    float* __restrict__ parth) {
    const int b = blockIdx.z, h = blockIdx.y;
    const int q0 = blockIdx.x * 256 + threadIdx.x;   // second query = q0 + 128
    __shared__ float Ks[64][32];
    __shared__ float vs[64];

    float qa[32], qb[32];
    {
        const float4* p  = (const float4*)&Qp[(size_t)(b*NN + q0) * DD + h * DKH];
        const float4* p2 = (const float4*)&Qp[(size_t)(b*NN + q0 + 128) * DD + h * DKH];
        #pragma unroll
        for (int i = 0; i < 8; i++) {
            float4 t = p[i];  qa[4*i] = t.x; qa[4*i+1] = t.y; qa[4*i+2] = t.z; qa[4*i+3] = t.w;
            float4 u = p2[i]; qb[4*i] = u.x; qb[4*i+1] = u.y; qb[4*i+2] = u.z; qb[4*i+3] = u.w;
        }
    }
    float la = 0.f, sa = 0.f, lb = 0.f, sb = 0.f;

    for (int kt = 0; kt < NN; kt += 64) {
        __syncthreads();
        #pragma unroll
        for (int i = 0; i < 16; i++) {
            int idx = i * 128 + threadIdx.x;
            int r = idx >> 5, c2 = idx & 31;
            Ks[r][c2] = Kp[(size_t)(b*NN + kt + r) * DD + h * DKH + c2];
        }
        if (threadIdx.x < 64) vs[threadIdx.x] = value[b*NN + kt + threadIdx.x];
        __syncthreads();
        #pragma unroll 2
        for (int k = 0; k < 64; k++) {
            const float4* kr = (const float4*)Ks[k];
            float d0=0.f,d1=0.f,d2=0.f,d3=0.f,e0=0.f,e1=0.f,e2=0.f,e3=0.f;
            #pragma unroll
            for (int i = 0; i < 8; i++) {
                float4 kv = kr[i];
                d0 += qa[4*i]   * kv.x; d1 += qa[4*i+1] * kv.y;
                d2 += qa[4*i+2] * kv.z; d3 += qa[4*i+3] * kv.w;
                e0 += qb[4*i]   * kv.x; e1 += qb[4*i+1] * kv.y;
                e2 += qb[4*i+2] * kv.z; e3 += qb[4*i+3] * kv.w;
            }
            float v  = vs[k];
            float xa = ((d0 + d1) + (d2 + d3)) * ATTN_SCALE;
            float xb = ((e0 + e1) + (e2 + e3)) * ATTN_SCALE;
            float ea = __expf(xa), eb = __expf(xb);
            la += ea; sa += ea * v;
            lb += eb; sb += eb * v;
        }
    }
    parth[(size_t)(b*NH + h) * NN + q0]       = sa / la;
    parth[(size_t)(b*NH + h) * NN + q0 + 128] = sb / lb;
}

// ---------------- combine: f = (1-lam)*part + lam*whole -> out[:, :, 0] ----------------
__global__ __launch_bounds__(256) void combine_kernel(const float* __restrict__ Qp,
                                                      const float* __restrict__ kg,
                                                      const float* __restrict__ parth,
                                                      const float* __restrict__ lamda,
                                                      float* __restrict__ out) {
    int idx = blockIdx.x * 256 + threadIdx.x;   // b*1024+n
    int b = idx >> 10, n = idx & 1023;
    const float4* q   = (const float4*)&Qp[(size_t)idx * DD];
    const float4* kgp = (const float4*)&kg[b * DD];
    float wsum = 0.f;
    #pragma unroll
    for (int h = 0; h < NH; h++) {
        float d = 0.f;
        #pragma unroll
        for (int i = 0; i < 8; i++) {
            float4 qv = q[h*8 + i], kv = kgp[h*8 + i];
            d += qv.x*kv.x + qv.y*kv.y + qv.z*kv.z + qv.w*kv.w;
        }
        wsum += fmaxf(d * ATTN_SCALE, 0.f);
    }
    float whole = wsum * 0.125f;
    float p = 0.f;
    #pragma unroll
    for (int h = 0; h < NH; h++) p += parth[(size_t)(b*NH + h) * NN + n];
    p *= 0.125f;
    float lam = lamda[0];
    out[(size_t)idx * 8] = (1.f - lam) * p + lam * whole;
}

// ---------------- fused PMMS-1 iteration (8 chunks of 128 tokens, half-split dot) ----------------
__global__ __launch_bounds__(256) void pmms1_iter_kernel(const float* __restrict__ qT,
                                                         const float* __restrict__ query,
                                                         const float* __restrict__ mu_a,
                                                         const float* __restrict__ mupart_in,
                                                         const float* __restrict__ colpart_in,
                                                         float* __restrict__ mupart_out,
                                                         float* __restrict__ colpart_out,
                                                         int first) {
    __shared__ float mus2[256][8];        // [c][k]
    __shared__ float zpart[2][CHT][6];    // per-half partial dots
    __shared__ float zz[CHT][8];          // normalized z
    __shared__ float red[8];
    const int chunk = blockIdx.x, b = blockIdx.y;
    const int tid = threadIdx.x;

    // ---- Phase 0: materialize current mu into smem ----
    if (first) {
        for (int i = tid; i < 256 * 5; i += 256) mus2[i / 5][i % 5] = mu_a[i];
        __syncthreads();
    } else {
        const int c = tid;
        float v[5];
        #pragma unroll
        for (int k = 0; k < 5; k++) {
            float cs = 0.f, a = 0.f;
            #pragma unroll
            for (int ch = 0; ch < NCH; ch++) {
                cs += colpart_in[(b*NCH + ch) * 5 + k];
                a  += mupart_in[(size_t)((b*NCH + ch) * 5 + k) * 256 + c];
            }
            v[k] = a / (1e-6f + cs);
        }
        #pragma unroll
        for (int k = 0; k < 5; k++) {
            float s = blockReduceSum256(v[k] * v[k], red);
            mus2[c][k] = v[k] / (1e-6f + sqrtf(s));
        }
        __syncthreads();
    }

    // ---- Phase A: z for this chunk's 128 tokens; dot split across 2 threads ----
    {
        const int token = tid & (CHT - 1);
        const int half  = tid >> 7;           // 0 or 1 (c range 0-127 / 128-255)
        const int n = chunk * CHT + token;
        const float* qp = &qT[((size_t)(b*DD) + half*128) * NN + n];
        float acc[5] = {0.f, 0.f, 0.f, 0.f, 0.f};
        #pragma unroll 8
        for (int c = 0; c < 128; c++) {
            float qv = qp[(size_t)c * NN];
            float4 m4 = *(const float4*)&mus2[half*128 + c][0];
            float m5 = mus2[half*128 + c][4];
            acc[0] += qv * m4.x; acc[1] += qv * m4.y; acc[2] += qv * m4.z;
            acc[3] += qv * m4.w; acc[4] += qv * m5;
        }
        #pragma unroll
        for (int k = 0; k < 5; k++) zpart[half][token][k] = acc[k];
        __syncthreads();

        float z[5] = {0.f, 0.f, 0.f, 0.f, 0.f};
        if (tid < CHT) {
            float s[5];
            #pragma unroll
            for (int k = 0; k < 5; k++) s[k] = zpart[0][tid][k] + zpart[1][tid][k];
            float m = s[0];
            #pragma unroll
            for (int k = 1; k < 5; k++) m = fmaxf(m, s[k]);
            float sum = 0.f;
            #pragma unroll
            for (int k = 0; k < 5; k++) { z[k] = __expf(20.f * (s[k] - m)); sum += z[k]; }
            float inv = 1.f / sum;
            #pragma unroll
            for (int k = 0; k < 5; k++) { z[k] *= inv; zz[tid][k] = z[k]; }
        }
        #pragma unroll
        for (int k = 0; k < 5; k++) {
            float s = blockReduceSum256(z[k], red);
            if (tid == 0) colpart_out[(b*NCH + chunk) * 5 + k] = s;
        }
    }

    // ---- Phase B: mu partials (thread = channel, 128 tokens) ----
    {
        const int c = tid;
        const float* qb = &query[(size_t)(b*NN + chunk*CHT) * DD + c];
        float acc[5] = {0.f, 0.f, 0.f, 0.f, 0.f};
        #pragma unroll 8
        for (int n = 0; n < CHT; n++) {
            float qv = qb[(size_t)n * DD];
            float4 z4 = *(const float4*)&zz[n][0];
            float z5 = zz[n][4];
            acc[0] += qv * z4.x; acc[1] += qv * z4.y; acc[2] += qv * z4.z;
            acc[3] += qv * z4.w; acc[4] += qv * z5;
        }
        #pragma unroll
        for (int k = 0; k < 5; k++)
            mupart_out[(size_t)((b*NCH + chunk) * 5 + k) * 256 + c] = acc[k];
    }
}

// ---------------- PMMS mu finalize: sum chunks, /colsum, l2norm over c ----------------
template<int K>
__global__ __launch_bounds__(256) void mustep_finalize(const float* __restrict__ mupart,
                                                       const float* __restrict__ colpart,
                                                       float* __restrict__ mu) {
    __shared__ float red[8];
    const int b = blockIdx.x, c = threadIdx.x;
    float acc[K];
    #pragma unroll
    for (int k = 0; k < K; k++) {
        float cs = 0.f, a = 0.f;
        #pragma unroll
        for (int ch = 0; ch < NCH; ch++) {
            cs += colpart[(b*NCH + ch) * K + k];
            a  += mupart[(size_t)((b*NCH + ch) * K + k) * 256 + c];
        }
        acc[k] = a / (1e-6f + cs);
    }
    #pragma unroll
    for (int k = 0; k < K; k++) {
        float s = blockReduceSum256(acc[k] * acc[k], red);
        acc[k] = acc[k] / (1e-6f + sqrtf(s));
    }
    #pragma unroll
    for (int k = 0; k < K; k++) mu[(b*256 + c) * K + k] = acc[k];
}

// ---------------- P = softmax(query @ mu), kappa=1, chunked + half-split ----------------
template<int K>
__global__ __launch_bounds__(256) void zstepT_kernel(const float* __restrict__ qT,
                                                     const float* __restrict__ mu,
                                                     float* __restrict__ P) {
    __shared__ float mus2[256][8];
    __shared__ float zpart[2][CHT][6];
    const int b = blockIdx.y, tid = threadIdx.x;
    for (int i = tid; i < 256 * K; i += 256) mus2[i / K][i % K] = mu[(b*256) * K + i];
    __syncthreads();
    const int token = tid & (CHT - 1);
    const int half  = tid >> 7;
    const int n = blockIdx.x * CHT + token;
    const float* qp = &qT[((size_t)(b*DD) + half*128) * NN + n];
    float acc[K];
    #pragma unroll
    for (int k = 0; k < K; k++) acc[k] = 0.f;
    #pragma unroll 8
    for (int c = 0; c < 128; c++) {
        float qv = qp[(size_t)c * NN];
        #pragma unroll
        for (int k = 0; k < K; k++) acc[k] += qv * mus2[half*128 + c][k];
    }
    #pragma unroll
    for (int k = 0; k < K; k++) zpart[half][token][k] = acc[k];
    __syncthreads();
    if (tid < CHT) {
        float s[K];
        #pragma unroll
        for (int k = 0; k < K; k++) s[k] = zpart[0][tid][k] + zpart[1][tid][k];
        float m = s[0];
        #pragma unroll
        for (int k = 1; k < K; k++) m = fmaxf(m, s[k]);
        float sum = 0.f;
        #pragma unroll
        for (int k = 0; k < K; k++) { s[k] = __expf(s[k] - m); sum += s[k]; }
        float inv = 1.f / sum;
        #pragma unroll
        for (int k = 0; k < K; k++) P[(size_t)(b*NN + n) * K + k] = s[k] * inv;
    }
}

// ---------------- PMMS-2: node = mu1 (b,256,5), 10 iterations fully in-block ----------------
__global__ __launch_bounds__(256) void pmms2_kernel(const float* __restrict__ mu1,
                                                    const float* __restrict__ mu_b,
                                                    float* __restrict__ mu2) {
    const int b = blockIdx.x, c = threadIdx.x;
    __shared__ float node[256][5];
    __shared__ float zsh[5][2];
    __shared__ float Ssh[10];
    __shared__ float red[8];
    #pragma unroll
    for (int n = 0; n < 5; n++) node[c][n] = mu1[(b*256 + c) * 5 + n];
    float mk0 = mu_b[c*2 + 0], mk1 = mu_b[c*2 + 1];

    for (int it = 0; it < 10; it++) {
        #pragma unroll
        for (int j = 0; j < 10; j++) {
            int n = j >> 1, k = j & 1;
            float v = node[c][n] * (k ? mk1 : mk0);
            float s = blockReduceSum256(v, red);
            if (c == 0) Ssh[j] = s;
        }
        __syncthreads();
        if (c == 0) {
            float csum0 = 0.f, csum1 = 0.f;
            float zt[5][2];
            #pragma unroll
            for (int n = 0; n < 5; n++) {
                float a = 20.f * Ssh[n*2 + 0];
                float q = 20.f * Ssh[n*2 + 1];
                float m = fmaxf(a, q);
                float ea = __expf(a - m), eb = __expf(q - m);
                float inv = 1.f / (ea + eb);
                zt[n][0] = ea * inv; zt[n][1] = eb * inv;
                csum0 += zt[n][0];   csum1 += zt[n][1];
            }
            #pragma unroll
            for (int n = 0; n < 5; n++) {
                zsh[n][0] = zt[n][0] / (1e-6f + csum0);
                zsh[n][1] = zt[n][1] / (1e-6f + csum1);
            }
        }
        __syncthreads();
        float nk0 = 0.f, nk1 = 0.f;
        #pragma unroll
        for (int n = 0; n < 5; n++) {
            nk0 += node[c][n] * zsh[n][0];
            nk1 += node[c][n] * zsh[n][1];
        }
        float s0 = blockReduceSum256(nk0 * nk0, red);
        float s1 = blockReduceSum256(nk1 * nk1, red);
        mk0 = nk0 / (1e-6f + sqrtf(s0));
        mk1 = nk1 / (1e-6f + sqrtf(s1));
        __syncthreads();
    }
    mu2[(b*256 + c) * 2 + 0] = mk0;
    mu2[(b*256 + c) * 2 + 1] = mk1;
}

// ---------------- node_weight: conv(1->16)+BN+ReLU+conv(16->1)+sigmoid gating ----------------
__global__ __launch_bounds__(1024) void nw_kernel(const float* __restrict__ P, int CH,
                                                  const float* __restrict__ w1,
                                                  const float* __restrict__ b1,
                                                  const float* __restrict__ g,
                                                  const float* __restrict__ be,
                                                  const float* __restrict__ w2,
                                                  const float* __restrict__ b2,
                                                  float* __restrict__ out, int outOff) {
    __shared__ float img[34][34];
    __shared__ float t1[8][34][34];
    __shared__ float sw1[144], sw2[144], sb1[16], sg[16], sbe[16];
    const int blk = blockIdx.x;
    const int b = blk / CH, ch = blk % CH;
    const int t = threadIdx.x;
    const int r = t >> 5, c = t & 31;

    for (int i = t; i < 34*34; i += 1024) ((float*)img)[i] = 0.f;
    for (int i = t; i < 8*34*34; i += 1024) ((float*)t1)[i] = 0.f;
    const float bninv = rsqrtf(1.f + 1e-5f);
    if (t < 144) { sw1[t] = w1[t]; sw2[t] = w2[t]; }
    if (t < 16)  { sb1[t] = b1[t]; sg[t] = g[t] * bninv; sbe[t] = be[t]; }
    __syncthreads();

    const int n = r * 32 + c;
    float xv = P[(size_t)((b << 10) + n) * CH + ch];
    img[r + 1][c + 1] = xv;
    float acc = b2[0];

    for (int half = 0; half < 2; half++) {
        __syncthreads();
        #pragma unroll
        for (int oc = 0; oc < 8; oc++) {
            int o = half * 8 + oc;
            float v = sb1[o];
            #pragma unroll
            for (int dy = 0; dy < 3; dy++)
                #pragma unroll
                for (int dx = 0; dx < 3; dx++)
                    v += sw1[o*9 + dy*3 + dx] * img[r + dy][c + dx];
            v = fmaxf(v * sg[o] + sbe[o], 0.f);
            t1[oc][r + 1][c + 1] = v;
        }
        __syncthreads();
        #pragma unroll
        for (int ic = 0; ic < 8; ic++) {
            int i2 = half * 8 + ic;
            #pragma unroll
            for (int dy = 0; dy < 3; dy++)
                #pragma unroll
                for (int dx = 0; dx < 3; dx++)
                    acc += sw2[i2*9 + dy*3 + dx] * t1[ic][r + dy][c + dx];
        }
    }
    float y = 1.f / (1.f + __expf(-acc));
    out[(size_t)((b << 10) + n) * 8 + outOff + ch] = xv * y;
}

// ---------------- launch ----------------
extern "C" void kernel_launch(void* const* d_in, const int* in_sizes, int n_in,
                              void* d_out, int out_size) {
    const float* query = (const float*)d_in[0];
    const float* key   = (const float*)d_in[1];
    const float* value = (const float*)d_in[2];
    const float* lamda = (const float*)d_in[3];
    const float* W0    = (const float*)d_in[4];
    const float* b0    = (const float*)d_in[5];
    const float* W1    = (const float*)d_in[6];
    const float* b1    = (const float*)d_in[7];
    const float* mu_a  = (const float*)d_in[8];
    const float* mu_b  = (const float*)d_in[9];
    const float* nw1_w1 = (const float*)d_in[10];
    const float* nw1_b1 = (const float*)d_in[11];
    const float* nw1_g  = (const float*)d_in[12];
    const float* nw1_be = (const float*)d_in[13];
    const float* nw1_w2 = (const float*)d_in[14];
    const float* nw1_b2 = (const float*)d_in[15];
    const float* nw2_w1 = (const float*)d_in[16];
    const float* nw2_b1 = (const float*)d_in[17];
    const float* nw2_g  = (const float*)d_in[18];
    const float* nw2_be = (const float*)d_in[19];
    const float* nw2_w2 = (const float*)d_in[20];
    const float* nw2_b2 = (const float*)d_in[21];
    float* out = (float*)d_out;

    float *Qp, *Kp, *qT, *kg, *kgpart, *parth, *mu1, *mu2, *P1, *P2;
    float *colpart, *mupart;
    cudaGetSymbolAddress((void**)&Qp, g_Qp);
    cudaGetSymbolAddress((void**)&Kp, g_Kp);
    cudaGetSymbolAddress((void**)&qT, g_qT);
    cudaGetSymbolAddress((void**)&kg, g_kg);
    cudaGetSymbolAddress((void**)&kgpart, g_kgpart);
    cudaGetSymbolAddress((void**)&parth, g_parth);
    cudaGetSymbolAddress((void**)&mu1, g_mu1);
    cudaGetSymbolAddress((void**)&mu2, g_mu2);
    cudaGetSymbolAddress((void**)&colpart, g_colpart);
    cudaGetSymbolAddress((void**)&mupart, g_mupart);
    cudaGetSymbolAddress((void**)&P1, g_P1);
    cudaGetSymbolAddress((void**)&P2, g_P2);

    float* mp[2] = {mupart, mupart + BB*NCH*5*DD};
    float* cp[2] = {colpart, colpart + BB*NCH*5};

    // Transpose query for coalesced PMMS access
    transpose_kernel<<<dim3(32, 8, 16), dim3(32, 8)>>>(query, qT);

    // Projections
    proj_kernel<<<dim3(2, 128), 256>>>(query, W0, b0, Qp);
    proj_kernel<<<dim3(2, 128), 256>>>(key,   W1, b1, Kp);

    // Attention
    kg_partial_kernel<<<dim3(8, BB), 256>>>(Kp, value, kgpart);
    kg_finalize_kernel<<<BB, 256>>>(kgpart, kg);
    flash_kernel<<<dim3(4, NH, BB), 128>>>(Qp, Kp, value, parth);
    combine_kernel<<<64, 256>>>(Qp, kg, parth, lamda, out);

    // PMMS-1 (K=5, 10 fused iterations, ping-pong partials, 8 chunks)
    for (int it = 0; it < 10; it++) {
        int ob = it & 1;
        int ib = ob ^ 1;
        pmms1_iter_kernel<<<dim3(NCH, BB), 256>>>(qT, query, mu_a,
                                                  mp[ib], cp[ib], mp[ob], cp[ob],
                                                  it == 0 ? 1 : 0);
    }
    mustep_finalize<5><<<BB, 256>>>(mp[1], cp[1], mu1);   // iter 9 wrote buffer 1

    // P1 = softmax(query @ mu1)
    zstepT_kernel<5><<<dim3(NCH, BB), 256>>>(qT, mu1, P1);

    // PMMS-2 (node = mu1, K=2)
    pmms2_kernel<<<BB, 256>>>(mu1, mu_b, mu2);
    zstepT_kernel<2><<<dim3(NCH, BB), 256>>>(qT, mu2, P2);

    // node_weight gating
    nw_kernel<<<BB * 5, 1024>>>(P1, 5, nw1_w1, nw1_b1, nw1_g, nw1_be, nw1_w2, nw1_b2, out, 1);
    nw_kernel<<<BB * 2, 1024>>>(P2, 2, nw2_w1, nw2_b1, nw2_g, nw2_be, nw2_w2, nw2_b2, out, 6);
}

// round 13
// speedup vs baseline: 1.9013x; 1.4371x over previous
#include <cuda_runtime.h>
#include <cuda_fp16.h>
#include <cstdint>
#include <math.h>

#define BB 16
#define NN 1024
#define DD 256
#define NH 8
#define DKH 32
#define NCH 8     // PMMS chunks per batch
#define CHT 128   // tokens per chunk
#define ATTN_SCALE 0.17677669529663687f  // 1/sqrt(32)

// ---------------- scratch (static device globals; no allocation) ----------------
__device__ float g_Qp[BB*NN*DD];       // 16 MB
__device__ float g_Kp[BB*NN*DD];       // 16 MB
__device__ float g_qT[BB*DD*NN];       // 16 MB  (query transposed: [b][c][n])
__device__ float g_kg[BB*DD];
__device__ float g_kgpart[BB*8*DD];
__device__ float g_parth[BB*NH*NN];
__device__ float g_mu1[BB*DD*5];
__device__ float g_mu2[BB*DD*2];
__device__ float g_colpart[2][BB*NCH*5];
__device__ float g_mupart[2][BB*NCH*5*DD];
__device__ float g_P1[BB*NN*5];
__device__ float g_P2[BB*NN*2];

// ---------------- helpers ----------------
__device__ __forceinline__ float blockReduceSum256(float v, float* red) {
    #pragma unroll
    for (int off = 16; off; off >>= 1) v += __shfl_down_sync(0xffffffffu, v, off);
    int w = threadIdx.x >> 5;
    if ((threadIdx.x & 31) == 0) red[w] = v;
    __syncthreads();
    if (threadIdx.x < 32) {
        float r = (threadIdx.x < 8) ? red[threadIdx.x] : 0.f;
        #pragma unroll
        for (int off = 4; off; off >>= 1) r += __shfl_down_sync(0xffffffffu, r, off);
        if (threadIdx.x == 0) red[0] = r;
    }
    __syncthreads();
    float out = red[0];
    __syncthreads();
    return out;
}

__device__ __forceinline__ uint32_t pack_h2(float a, float b) {
    __half2 h = __floats2half2_rn(a, b);
    return *(uint32_t*)&h;
}

__device__ __forceinline__ void mma_f16(float& c0, float& c1, float& c2, float& c3,
                                        uint32_t a0, uint32_t a1, uint32_t a2, uint32_t a3,
                                        uint32_t b0, uint32_t b1) {
    asm("mma.sync.aligned.m16n8k16.row.col.f32.f16.f16.f32 "
        "{%0,%1,%2,%3}, {%4,%5,%6,%7}, {%8,%9}, {%0,%1,%2,%3};"
        : "+f"(c0), "+f"(c1), "+f"(c2), "+f"(c3)
        : "r"(a0), "r"(a1), "r"(a2), "r"(a3), "r"(b0), "r"(b1));
}

// ---------------- transpose: qT[b][c][n] = query[b][n][c] ----------------
__global__ __launch_bounds__(256) void transpose_kernel(const float* __restrict__ q,
                                                        float* __restrict__ qT) {
    __shared__ float tile[32][33];
    const int b = blockIdx.z;
    const int n0 = blockIdx.x * 32;
    const int c0 = blockIdx.y * 32;
    const int tx = threadIdx.x, ty = threadIdx.y;
    #pragma unroll
    for (int j = 0; j < 4; j++)
        tile[ty + 8*j][tx] = q[(size_t)(b*NN + n0 + ty + 8*j) * DD + c0 + tx];
    __syncthreads();
    #pragma unroll
    for (int j = 0; j < 4; j++)
        qT[(size_t)(b*DD + c0 + ty + 8*j) * NN + n0 + tx] = tile[tx][ty + 8*j];
}

// ---------------- projection GEMM: C[16384,256] = A[16384,256] @ W^T + bias ----------------
__global__ __launch_bounds__(256) void proj_kernel(const float* __restrict__ A,
                                                   const float* __restrict__ W,
                                                   const float* __restrict__ bias,
                                                   float* __restrict__ C) {
    __shared__ float As[8][132];
    __shared__ float Bs[8][132];
    const int bm = blockIdx.y * 128;
    const int bn = blockIdx.x * 128;
    const int t  = threadIdx.x;
    const int tx = t & 15, ty = t >> 4;
    const int tn0 = tx * 8, tm0 = ty * 8;
    const int lrow = t >> 1, lk = (t & 1) * 4;

    float acc[8][8];
    #pragma unroll
    for (int i = 0; i < 8; i++)
        #pragma unroll
        for (int j = 0; j < 8; j++) acc[i][j] = 0.f;

    for (int k0 = 0; k0 < 256; k0 += 8) {
        float4 a = *(const float4*)&A[(size_t)(bm + lrow) * 256 + k0 + lk];
        float4 w = *(const float4*)&W[(size_t)(bn + lrow) * 256 + k0 + lk];
        As[lk+0][lrow] = a.x; As[lk+1][lrow] = a.y; As[lk+2][lrow] = a.z; As[lk+3][lrow] = a.w;
        Bs[lk+0][lrow] = w.x; Bs[lk+1][lrow] = w.y; Bs[lk+2][lrow] = w.z; Bs[lk+3][lrow] = w.w;
        __syncthreads();
        #pragma unroll
        for (int k = 0; k < 8; k++) {
            float4 ra0 = *(const float4*)&As[k][tm0];
            float4 ra1 = *(const float4*)&As[k][tm0 + 4];
            float4 rb0 = *(const float4*)&Bs[k][tn0];
            float4 rb1 = *(const float4*)&Bs[k][tn0 + 4];
            float ra[8] = {ra0.x, ra0.y, ra0.z, ra0.w, ra1.x, ra1.y, ra1.z, ra1.w};
            float rb[8] = {rb0.x, rb0.y, rb0.z, rb0.w, rb1.x, rb1.y, rb1.z, rb1.w};
            #pragma unroll
            for (int i = 0; i < 8; i++)
                #pragma unroll
                for (int j = 0; j < 8; j++) acc[i][j] += ra[i] * rb[j];
        }
        __syncthreads();
    }
    #pragma unroll
    for (int i = 0; i < 8; i++) {
        #pragma unroll
        for (int j = 0; j < 8; j++) acc[i][j] += bias[bn + tn0 + j];
        float4* dst = (float4*)&C[(size_t)(bm + tm0 + i) * 256 + bn + tn0];
        dst[0] = make_float4(acc[i][0], acc[i][1], acc[i][2], acc[i][3]);
        dst[1] = make_float4(acc[i][4], acc[i][5], acc[i][6], acc[i][7]);
    }
}

// ---------------- key_global partials ----------------
__global__ __launch_bounds__(256) void kg_partial_kernel(const float* __restrict__ Kp,
                                                         const float* __restrict__ value,
                                                         float* __restrict__ kgpart) {
    __shared__ float vs[128];
    const int chunk = blockIdx.x, b = blockIdx.y;
    const int c = threadIdx.x;
    const int n0 = chunk * 128;
    if (c < 128) vs[c] = value[b*NN + n0 + c];
    __syncthreads();
    const float* kp = &Kp[(size_t)(b*NN + n0) * DD + c];
    float a0 = 0.f, a1 = 0.f, a2 = 0.f, a3 = 0.f;
    #pragma unroll 4
    for (int n = 0; n < 128; n += 4) {
        a0 += kp[(size_t)(n+0) * DD] * vs[n+0];
        a1 += kp[(size_t)(n+1) * DD] * vs[n+1];
        a2 += kp[(size_t)(n+2) * DD] * vs[n+2];
        a3 += kp[(size_t)(n+3) * DD] * vs[n+3];
    }
    kgpart[(size_t)(b*8 + chunk) * DD + c] = (a0 + a1) + (a2 + a3);
}

__global__ __launch_bounds__(256) void kg_finalize_kernel(const float* __restrict__ kgpart,
                                                          float* __restrict__ kg) {
    const int b = blockIdx.x, c = threadIdx.x;
    float s = 0.f;
    #pragma unroll
    for (int ch = 0; ch < 8; ch++) s += kgpart[(size_t)(b*8 + ch) * DD + c];
    kg[b*DD + c] = s * (1.0f / NN);
}

// ---------------- FP16 m16n8k16 flash attention with scalar V ----------------
// block: 128 queries for one (b,h); 8 warps = 4(m:32q) x 2(n:64keys); key tiles of 128
__global__ __launch_bounds__(256) void flash_mma16_kernel(const float* __restrict__ Qp,
                                                          const float* __restrict__ Kp,
                                                          const float* __restrict__ value,
                                                          float* __restrict__ parth) {
    __shared__ uint32_t Qs[128][20];   // 16 half2 per row (+4 pad)
    __shared__ uint32_t Ks[128][20];
    __shared__ float vs[128];
    __shared__ float lred[2][128];
    __shared__ float sred[2][128];
    const int b = blockIdx.z, h = blockIdx.y;
    const int q0 = blockIdx.x * 128;
    const int tid = threadIdx.x;
    const int wid = tid >> 5, lane = tid & 31;
    const int wm = wid & 3, wn = wid >> 2;
    const int gid = lane >> 2, tig = lane & 3;

    // load Q tile (128 x 32 fp32 -> 128 x 16 half2)
    {
        const float* src = &Qp[(size_t)(b*NN + q0) * DD + h * DKH];
        #pragma unroll
        for (int i = tid; i < 128*16; i += 256) {
            int r = i >> 4, c2 = i & 15;
            float2 v = *(const float2*)&src[(size_t)r * DD + c2*2];
            Qs[r][c2] = pack_h2(v.x, v.y);
        }
    }
    __syncthreads();

    // persistent A fragments: 2 m-tiles x 2 k-steps x 4 regs
    uint32_t afr[2][2][4];
    #pragma unroll
    for (int mt = 0; mt < 2; mt++)
        #pragma unroll
        for (int ks = 0; ks < 2; ks++) {
            int r = wm*32 + mt*16 + gid;
            int h2 = ks*8 + tig;
            afr[mt][ks][0] = Qs[r][h2];       afr[mt][ks][1] = Qs[r+8][h2];
            afr[mt][ks][2] = Qs[r][h2 + 4];   afr[mt][ks][3] = Qs[r+8][h2 + 4];
        }

    float la[2][2] = {{0.f,0.f},{0.f,0.f}};
    float sa[2][2] = {{0.f,0.f},{0.f,0.f}};

    for (int kt = 0; kt < NN; kt += 128) {
        __syncthreads();
        const float* ksrc = &Kp[(size_t)(b*NN + kt) * DD + h * DKH];
        #pragma unroll
        for (int i = tid; i < 128*16; i += 256) {
            int r = i >> 4, c2 = i & 15;
            float2 v = *(const float2*)&ksrc[(size_t)r * DD + c2*2];
            Ks[r][c2] = pack_h2(v.x, v.y);
        }
        if (tid < 128) vs[tid] = value[b*NN + kt + tid];
        __syncthreads();

        #pragma unroll
        for (int nt = 0; nt < 8; nt++) {
            int nb = wn*64 + nt*8;
            uint32_t bfr[2][2];
            #pragma unroll
            for (int ks = 0; ks < 2; ks++) {
                bfr[ks][0] = Ks[nb + gid][ks*8 + tig];
                bfr[ks][1] = Ks[nb + gid][ks*8 + tig + 4];
            }
            float v0 = vs[nb + 2*tig], v1 = vs[nb + 2*tig + 1];
            #pragma unroll
            for (int mt = 0; mt < 2; mt++) {
                float c0 = 0.f, c1 = 0.f, c2 = 0.f, c3 = 0.f;
                #pragma unroll
                for (int ks = 0; ks < 2; ks++)
                    mma_f16(c0, c1, c2, c3,
                            afr[mt][ks][0], afr[mt][ks][1], afr[mt][ks][2], afr[mt][ks][3],
                            bfr[ks][0], bfr[ks][1]);
                float e0 = __expf(c0 * ATTN_SCALE);
                float e1 = __expf(c1 * ATTN_SCALE);
                float e2 = __expf(c2 * ATTN_SCALE);
                float e3 = __expf(c3 * ATTN_SCALE);
                la[mt][0] += e0 + e1;  sa[mt][0] += e0*v0 + e1*v1;
                la[mt][1] += e2 + e3;  sa[mt][1] += e2*v0 + e3*v1;
            }
        }
    }

    // reduce across the 4 lanes of each quad (they share the same q row)
    #pragma unroll
    for (int mt = 0; mt < 2; mt++)
        #pragma unroll
        for (int rr = 0; rr < 2; rr++) {
            float l = la[mt][rr], s = sa[mt][rr];
            l += __shfl_xor_sync(0xffffffffu, l, 1);
            l += __shfl_xor_sync(0xffffffffu, l, 2);
            s += __shfl_xor_sync(0xffffffffu, s, 1);
            s += __shfl_xor_sync(0xffffffffu, s, 2);
            la[mt][rr] = l; sa[mt][rr] = s;
        }
    if (tig == 0) {
        #pragma unroll
        for (int mt = 0; mt < 2; mt++) {
            int r0 = wm*32 + mt*16 + gid;
            lred[wn][r0]     = la[mt][0];  sred[wn][r0]     = sa[mt][0];
            lred[wn][r0 + 8] = la[mt][1];  sred[wn][r0 + 8] = sa[mt][1];
        }
    }
    __syncthreads();
    if (tid < 128) {
        float l = lred[0][tid] + lred[1][tid];
        float s = sred[0][tid] + sred[1][tid];
        parth[(size_t)(b*NH + h) * NN + q0 + tid] = s / l;
    }
}

// ---------------- combine: f = (1-lam)*part + lam*whole -> out[:, :, 0] ----------------
__global__ __launch_bounds__(256) void combine_kernel(const float* __restrict__ Qp,
                                                      const float* __restrict__ kg,
                                                      const float* __restrict__ parth,
                                                      const float* __restrict__ lamda,
                                                      float* __restrict__ out) {
    int idx = blockIdx.x * 256 + threadIdx.x;   // b*1024+n
    int b = idx >> 10, n = idx & 1023;
    const float4* q   = (const float4*)&Qp[(size_t)idx * DD];
    const float4* kgp = (const float4*)&kg[b * DD];
    float wsum = 0.f;
    #pragma unroll
    for (int h = 0; h < NH; h++) {
        float d = 0.f;
        #pragma unroll
        for (int i = 0; i < 8; i++) {
            float4 qv = q[h*8 + i], kv = kgp[h*8 + i];
            d += qv.x*kv.x + qv.y*kv.y + qv.z*kv.z + qv.w*kv.w;
        }
        wsum += fmaxf(d * ATTN_SCALE, 0.f);
    }
    float whole = wsum * 0.125f;
    float p = 0.f;
    #pragma unroll
    for (int h = 0; h < NH; h++) p += parth[(size_t)(b*NH + h) * NN + n];
    p *= 0.125f;
    float lam = lamda[0];
    out[(size_t)idx * 8] = (1.f - lam) * p + lam * whole;
}

// ---------------- fused PMMS-1 iteration (8 chunks of 128 tokens, half-split dot) ----------------
__global__ __launch_bounds__(256) void pmms1_iter_kernel(const float* __restrict__ qT,
                                                         const float* __restrict__ query,
                                                         const float* __restrict__ mu_a,
                                                         const float* __restrict__ mupart_in,
                                                         const float* __restrict__ colpart_in,
                                                         float* __restrict__ mupart_out,
                                                         float* __restrict__ colpart_out,
                                                         int first) {
    __shared__ float mus2[256][8];        // [c][k]
    __shared__ float zpart[2][CHT][6];    // per-half partial dots
    __shared__ float zz[CHT][8];          // normalized z
    __shared__ float red[8];
    const int chunk = blockIdx.x, b = blockIdx.y;
    const int tid = threadIdx.x;

    // ---- Phase 0: materialize current mu into smem ----
    if (first) {
        for (int i = tid; i < 256 * 5; i += 256) mus2[i / 5][i % 5] = mu_a[i];
        __syncthreads();
    } else {
        const int c = tid;
        float v[5];
        #pragma unroll
        for (int k = 0; k < 5; k++) {
            float cs = 0.f, a = 0.f;
            #pragma unroll
            for (int ch = 0; ch < NCH; ch++) {
                cs += colpart_in[(b*NCH + ch) * 5 + k];
                a  += mupart_in[(size_t)((b*NCH + ch) * 5 + k) * 256 + c];
            }
            v[k] = a / (1e-6f + cs);
        }
        #pragma unroll
        for (int k = 0; k < 5; k++) {
            float s = blockReduceSum256(v[k] * v[k], red);
            mus2[c][k] = v[k] / (1e-6f + sqrtf(s));
        }
        __syncthreads();
    }

    // ---- Phase A: z for this chunk's 128 tokens; dot split across 2 threads ----
    {
        const int token = tid & (CHT - 1);
        const int half  = tid >> 7;           // 0 or 1 (c range 0-127 / 128-255)
        const int n = chunk * CHT + token;
        const float* qp = &qT[((size_t)(b*DD) + half*128) * NN + n];
        float acc[5] = {0.f, 0.f, 0.f, 0.f, 0.f};
        #pragma unroll 8
        for (int c = 0; c < 128; c++) {
            float qv = qp[(size_t)c * NN];
            float4 m4 = *(const float4*)&mus2[half*128 + c][0];
            float m5 = mus2[half*128 + c][4];
            acc[0] += qv * m4.x; acc[1] += qv * m4.y; acc[2] += qv * m4.z;
            acc[3] += qv * m4.w; acc[4] += qv * m5;
        }
        #pragma unroll
        for (int k = 0; k < 5; k++) zpart[half][token][k] = acc[k];
        __syncthreads();

        float z[5] = {0.f, 0.f, 0.f, 0.f, 0.f};
        if (tid < CHT) {
            float s[5];
            #pragma unroll
            for (int k = 0; k < 5; k++) s[k] = zpart[0][tid][k] + zpart[1][tid][k];
            float m = s[0];
            #pragma unroll
            for (int k = 1; k < 5; k++) m = fmaxf(m, s[k]);
            float sum = 0.f;
            #pragma unroll
            for (int k = 0; k < 5; k++) { z[k] = __expf(20.f * (s[k] - m)); sum += z[k]; }
            float inv = 1.f / sum;
            #pragma unroll
            for (int k = 0; k < 5; k++) { z[k] *= inv; zz[tid][k] = z[k]; }
        }
        #pragma unroll
        for (int k = 0; k < 5; k++) {
            float s = blockReduceSum256(z[k], red);
            if (tid == 0) colpart_out[(b*NCH + chunk) * 5 + k] = s;
        }
    }

    // ---- Phase B: mu partials (thread = channel, 128 tokens) ----
    {
        const int c = tid;
        const float* qb = &query[(size_t)(b*NN + chunk*CHT) * DD + c];
        float acc[5] = {0.f, 0.f, 0.f, 0.f, 0.f};
        #pragma unroll 8
        for (int n = 0; n < CHT; n++) {
            float qv = qb[(size_t)n * DD];
            float4 z4 = *(const float4*)&zz[n][0];
            float z5 = zz[n][4];
            acc[0] += qv * z4.x; acc[1] += qv * z4.y; acc[2] += qv * z4.z;
            acc[3] += qv * z4.w; acc[4] += qv * z5;
        }
        #pragma unroll
        for (int k = 0; k < 5; k++)
            mupart_out[(size_t)((b*NCH + chunk) * 5 + k) * 256 + c] = acc[k];
    }
}

// ---------------- PMMS mu finalize: sum chunks, /colsum, l2norm over c ----------------
template<int K>
__global__ __launch_bounds__(256) void mustep_finalize(const float* __restrict__ mupart,
                                                       const float* __restrict__ colpart,
                                                       float* __restrict__ mu) {
    __shared__ float red[8];
    const int b = blockIdx.x, c = threadIdx.x;
    float acc[K];
    #pragma unroll
    for (int k = 0; k < K; k++) {
        float cs = 0.f, a = 0.f;
        #pragma unroll
        for (int ch = 0; ch < NCH; ch++) {
            cs += colpart[(b*NCH + ch) * K + k];
            a  += mupart[(size_t)((b*NCH + ch) * K + k) * 256 + c];
        }
        acc[k] = a / (1e-6f + cs);
    }
    #pragma unroll
    for (int k = 0; k < K; k++) {
        float s = blockReduceSum256(acc[k] * acc[k], red);
        acc[k] = acc[k] / (1e-6f + sqrtf(s));
    }
    #pragma unroll
    for (int k = 0; k < K; k++) mu[(b*256 + c) * K + k] = acc[k];
}

// ---------------- P = softmax(query @ mu), kappa=1, chunked + half-split ----------------
template<int K>
__global__ __launch_bounds__(256) void zstepT_kernel(const float* __restrict__ qT,
                                                     const float* __restrict__ mu,
                                                     float* __restrict__ P) {
    __shared__ float mus2[256][8];
    __shared__ float zpart[2][CHT][6];
    const int b = blockIdx.y, tid = threadIdx.x;
    for (int i = tid; i < 256 * K; i += 256) mus2[i / K][i % K] = mu[(b*256) * K + i];
    __syncthreads();
    const int token = tid & (CHT - 1);
    const int half  = tid >> 7;
    const int n = blockIdx.x * CHT + token;
    const float* qp = &qT[((size_t)(b*DD) + half*128) * NN + n];
    float acc[K];
    #pragma unroll
    for (int k = 0; k < K; k++) acc[k] = 0.f;
    #pragma unroll 8
    for (int c = 0; c < 128; c++) {
        float qv = qp[(size_t)c * NN];
        #pragma unroll
        for (int k = 0; k < K; k++) acc[k] += qv * mus2[half*128 + c][k];
    }
    #pragma unroll
    for (int k = 0; k < K; k++) zpart[half][token][k] = acc[k];
    __syncthreads();
    if (tid < CHT) {
        float s[K];
        #pragma unroll
        for (int k = 0; k < K; k++) s[k] = zpart[0][tid][k] + zpart[1][tid][k];
        float m = s[0];
        #pragma unroll
        for (int k = 1; k < K; k++) m = fmaxf(m, s[k]);
        float sum = 0.f;
        #pragma unroll
        for (int k = 0; k < K; k++) { s[k] = __expf(s[k] - m); sum += s[k]; }
        float inv = 1.f / sum;
        #pragma unroll
        for (int k = 0; k < K; k++) P[(size_t)(b*NN + n) * K + k] = s[k] * inv;
    }
}

// ---------------- PMMS-2: node = mu1 (b,256,5), 10 iterations fully in-block ----------------
__global__ __launch_bounds__(256) void pmms2_kernel(const float* __restrict__ mu1,
                                                    const float* __restrict__ mu_b,
                                                    float* __restrict__ mu2) {
    const int b = blockIdx.x, c = threadIdx.x;
    __shared__ float node[256][5];
    __shared__ float zsh[5][2];
    __shared__ float Ssh[10];
    __shared__ float red[8];
    #pragma unroll
    for (int n = 0; n < 5; n++) node[c][n] = mu1[(b*256 + c) * 5 + n];
    float mk0 = mu_b[c*2 + 0], mk1 = mu_b[c*2 + 1];

    for (int it = 0; it < 10; it++) {
        #pragma unroll
        for (int j = 0; j < 10; j++) {
            int n = j >> 1, k = j & 1;
            float v = node[c][n] * (k ? mk1 : mk0);
            float s = blockReduceSum256(v, red);
            if (c == 0) Ssh[j] = s;
        }
        __syncthreads();
        if (c == 0) {
            float csum0 = 0.f, csum1 = 0.f;
            float zt[5][2];
            #pragma unroll
            for (int n = 0; n < 5; n++) {
                float a = 20.f * Ssh[n*2 + 0];
                float q = 20.f * Ssh[n*2 + 1];
                float m = fmaxf(a, q);
                float ea = __expf(a - m), eb = __expf(q - m);
                float inv = 1.f / (ea + eb);
                zt[n][0] = ea * inv; zt[n][1] = eb * inv;
                csum0 += zt[n][0];   csum1 += zt[n][1];
            }
            #pragma unroll
            for (int n = 0; n < 5; n++) {
                zsh[n][0] = zt[n][0] / (1e-6f + csum0);
                zsh[n][1] = zt[n][1] / (1e-6f + csum1);
            }
        }
        __syncthreads();
        float nk0 = 0.f, nk1 = 0.f;
        #pragma unroll
        for (int n = 0; n < 5; n++) {
            nk0 += node[c][n] * zsh[n][0];
            nk1 += node[c][n] * zsh[n][1];
        }
        float s0 = blockReduceSum256(nk0 * nk0, red);
        float s1 = blockReduceSum256(nk1 * nk1, red);
        mk0 = nk0 / (1e-6f + sqrtf(s0));
        mk1 = nk1 / (1e-6f + sqrtf(s1));
        __syncthreads();
    }
    mu2[(b*256 + c) * 2 + 0] = mk0;
    mu2[(b*256 + c) * 2 + 1] = mk1;
}

// ---------------- node_weight: conv(1->16)+BN+ReLU+conv(16->1)+sigmoid gating ----------------
__global__ __launch_bounds__(1024) void nw_kernel(const float* __restrict__ P, int CH,
                                                  const float* __restrict__ w1,
                                                  const float* __restrict__ b1,
                                                  const float* __restrict__ g,
                                                  const float* __restrict__ be,
                                                  const float* __restrict__ w2,
                                                  const float* __restrict__ b2,
                                                  float* __restrict__ out, int outOff) {
    __shared__ float img[34][34];
    __shared__ float t1[8][34][34];
    __shared__ float sw1[144], sw2[144], sb1[16], sg[16], sbe[16];
    const int blk = blockIdx.x;
    const int b = blk / CH, ch = blk % CH;
    const int t = threadIdx.x;
    const int r = t >> 5, c = t & 31;

    for (int i = t; i < 34*34; i += 1024) ((float*)img)[i] = 0.f;
    for (int i = t; i < 8*34*34; i += 1024) ((float*)t1)[i] = 0.f;
    const float bninv = rsqrtf(1.f + 1e-5f);
    if (t < 144) { sw1[t] = w1[t]; sw2[t] = w2[t]; }
    if (t < 16)  { sb1[t] = b1[t]; sg[t] = g[t] * bninv; sbe[t] = be[t]; }
    __syncthreads();

    const int n = r * 32 + c;
    float xv = P[(size_t)((b << 10) + n) * CH + ch];
    img[r + 1][c + 1] = xv;
    float acc = b2[0];

    for (int half = 0; half < 2; half++) {
        __syncthreads();
        #pragma unroll
        for (int oc = 0; oc < 8; oc++) {
            int o = half * 8 + oc;
            float v = sb1[o];
            #pragma unroll
            for (int dy = 0; dy < 3; dy++)
                #pragma unroll
                for (int dx = 0; dx < 3; dx++)
                    v += sw1[o*9 + dy*3 + dx] * img[r + dy][c + dx];
            v = fmaxf(v * sg[o] + sbe[o], 0.f);
            t1[oc][r + 1][c + 1] = v;
        }
        __syncthreads();
        #pragma unroll
        for (int ic = 0; ic < 8; ic++) {
            int i2 = half * 8 + ic;
            #pragma unroll
            for (int dy = 0; dy < 3; dy++)
                #pragma unroll
                for (int dx = 0; dx < 3; dx++)
                    acc += sw2[i2*9 + dy*3 + dx] * t1[ic][r + dy][c + dx];
        }
    }
    float y = 1.f / (1.f + __expf(-acc));
    out[(size_t)((b << 10) + n) * 8 + outOff + ch] = xv * y;
}

// ---------------- launch ----------------
extern "C" void kernel_launch(void* const* d_in, const int* in_sizes, int n_in,
                              void* d_out, int out_size) {
    const float* query = (const float*)d_in[0];
    const float* key   = (const float*)d_in[1];
    const float* value = (const float*)d_in[2];
    const float* lamda = (const float*)d_in[3];
    const float* W0    = (const float*)d_in[4];
    const float* b0    = (const float*)d_in[5];
    const float* W1    = (const float*)d_in[6];
    const float* b1    = (const float*)d_in[7];
    const float* mu_a  = (const float*)d_in[8];
    const float* mu_b  = (const float*)d_in[9];
    const float* nw1_w1 = (const float*)d_in[10];
    const float* nw1_b1 = (const float*)d_in[11];
    const float* nw1_g  = (const float*)d_in[12];
    const float* nw1_be = (const float*)d_in[13];
    const float* nw1_w2 = (const float*)d_in[14];
    const float* nw1_b2 = (const float*)d_in[15];
    const float* nw2_w1 = (const float*)d_in[16];
    const float* nw2_b1 = (const float*)d_in[17];
    const float* nw2_g  = (const float*)d_in[18];
    const float* nw2_be = (const float*)d_in[19];
    const float* nw2_w2 = (const float*)d_in[20];
    const float* nw2_b2 = (const float*)d_in[21];
    float* out = (float*)d_out;

    float *Qp, *Kp, *qT, *kg, *kgpart, *parth, *mu1, *mu2, *P1, *P2;
    float *colpart, *mupart;
    cudaGetSymbolAddress((void**)&Qp, g_Qp);
    cudaGetSymbolAddress((void**)&Kp, g_Kp);
    cudaGetSymbolAddress((void**)&qT, g_qT);
    cudaGetSymbolAddress((void**)&kg, g_kg);
    cudaGetSymbolAddress((void**)&kgpart, g_kgpart);
    cudaGetSymbolAddress((void**)&parth, g_parth);
    cudaGetSymbolAddress((void**)&mu1, g_mu1);
    cudaGetSymbolAddress((void**)&mu2, g_mu2);
    cudaGetSymbolAddress((void**)&colpart, g_colpart);
    cudaGetSymbolAddress((void**)&mupart, g_mupart);
    cudaGetSymbolAddress((void**)&P1, g_P1);
    cudaGetSymbolAddress((void**)&P2, g_P2);

    float* mp[2] = {mupart, mupart + BB*NCH*5*DD};
    float* cp[2] = {colpart, colpart + BB*NCH*5};

    // Transpose query for coalesced PMMS access
    transpose_kernel<<<dim3(32, 8, 16), dim3(32, 8)>>>(query, qT);

    // Projections
    proj_kernel<<<dim3(2, 128), 256>>>(query, W0, b0, Qp);
    proj_kernel<<<dim3(2, 128), 256>>>(key,   W1, b1, Kp);

    // Attention
    kg_partial_kernel<<<dim3(8, BB), 256>>>(Kp, value, kgpart);
    kg_finalize_kernel<<<BB, 256>>>(kgpart, kg);
    flash_mma16_kernel<<<dim3(8, NH, BB), 256>>>(Qp, Kp, value, parth);
    combine_kernel<<<64, 256>>>(Qp, kg, parth, lamda, out);

    // PMMS-1 (K=5, 10 fused iterations, ping-pong partials, 8 chunks)
    for (int it = 0; it < 10; it++) {
        int ob = it & 1;
        int ib = ob ^ 1;
        pmms1_iter_kernel<<<dim3(NCH, BB), 256>>>(qT, query, mu_a,
                                                  mp[ib], cp[ib], mp[ob], cp[ob],
                                                  it == 0 ? 1 : 0);
    }
    mustep_finalize<5><<<BB, 256>>>(mp[1], cp[1], mu1);   // iter 9 wrote buffer 1

    // P1 = softmax(query @ mu1)
    zstepT_kernel<5><<<dim3(NCH, BB), 256>>>(qT, mu1, P1);

    // PMMS-2 (node = mu1, K=2)
    pmms2_kernel<<<BB, 256>>>(mu1, mu_b, mu2);
    zstepT_kernel<2><<<dim3(NCH, BB), 256>>>(qT, mu2, P2);

    // node_weight gating
    nw_kernel<<<BB * 5, 1024>>>(P1, 5, nw1_w1, nw1_b1, nw1_g, nw1_be, nw1_w2, nw1_b2, out, 1);
    nw_kernel<<<BB * 2, 1024>>>(P2, 2, nw2_w1, nw2_b1, nw2_g, nw2_be, nw2_w2, nw2_b2, out, 6);
}

// round 14
// speedup vs baseline: 2.3073x; 1.2135x over previous
#include <cuda_runtime.h>
#include <cuda_fp16.h>
#include <cstdint>
#include <math.h>

#define BB 16
#define NN 1024
#define DD 256
#define NH 8
#define DKH 32
#define NCH 8     // PMMS chunks per batch
#define CHT 128   // tokens per chunk
#define ATTN_SCALE 0.17677669529663687f  // 1/sqrt(32)

// ---------------- scratch (static device globals; no allocation) ----------------
__device__ float g_Qp[BB*NN*DD];       // 16 MB
__device__ float g_Kp[BB*NN*DD];       // 16 MB
__device__ float g_qT[BB*DD*NN];       // 16 MB  (query transposed: [b][c][n])
__device__ float g_kg[BB*DD];
__device__ float g_kgpart[BB*8*DD];
__device__ float g_parth[BB*NH*NN];
__device__ float g_mu1[BB*DD*5];
__device__ float g_mu2[BB*DD*2];
__device__ float g_colpart[2][BB*NCH*5];
__device__ float g_mupart[2][BB*NCH*5*DD];
__device__ float g_P1[BB*NN*5];
__device__ float g_P2[BB*NN*2];

// ---------------- helpers ----------------
__device__ __forceinline__ float blockReduceSum256(float v, float* red) {
    #pragma unroll
    for (int off = 16; off; off >>= 1) v += __shfl_down_sync(0xffffffffu, v, off);
    int w = threadIdx.x >> 5;
    if ((threadIdx.x & 31) == 0) red[w] = v;
    __syncthreads();
    if (threadIdx.x < 32) {
        float r = (threadIdx.x < 8) ? red[threadIdx.x] : 0.f;
        #pragma unroll
        for (int off = 4; off; off >>= 1) r += __shfl_down_sync(0xffffffffu, r, off);
        if (threadIdx.x == 0) red[0] = r;
    }
    __syncthreads();
    float out = red[0];
    __syncthreads();
    return out;
}

__device__ __forceinline__ uint32_t pack_h2(float a, float b) {
    __half2 h = __floats2half2_rn(a, b);
    return *(uint32_t*)&h;
}

__device__ __forceinline__ void mma_f16(float& c0, float& c1, float& c2, float& c3,
                                        uint32_t a0, uint32_t a1, uint32_t a2, uint32_t a3,
                                        uint32_t b0, uint32_t b1) {
    asm("mma.sync.aligned.m16n8k16.row.col.f32.f16.f16.f32 "
        "{%0,%1,%2,%3}, {%4,%5,%6,%7}, {%8,%9}, {%0,%1,%2,%3};"
        : "+f"(c0), "+f"(c1), "+f"(c2), "+f"(c3)
        : "r"(a0), "r"(a1), "r"(a2), "r"(a3), "r"(b0), "r"(b1));
}

// ---------------- transpose: qT[b][c][n] = query[b][n][c] ----------------
__global__ __launch_bounds__(256) void transpose_kernel(const float* __restrict__ q,
                                                        float* __restrict__ qT) {
    __shared__ float tile[32][33];
    const int b = blockIdx.z;
    const int n0 = blockIdx.x * 32;
    const int c0 = blockIdx.y * 32;
    const int tx = threadIdx.x, ty = threadIdx.y;
    #pragma unroll
    for (int j = 0; j < 4; j++)
        tile[ty + 8*j][tx] = q[(size_t)(b*NN + n0 + ty + 8*j) * DD + c0 + tx];
    __syncthreads();
    #pragma unroll
    for (int j = 0; j < 4; j++)
        qT[(size_t)(b*DD + c0 + ty + 8*j) * NN + n0 + tx] = tile[tx][ty + 8*j];
}

// ---------------- FP16 MMA projection GEMM: C[16384,256] = A @ W^T + bias ----------------
// block tile 128(m) x 128(n), k-tile 32; 8 warps as 4(m) x 2(n); warp tile 32x64
__global__ __launch_bounds__(256) void proj_mma16_kernel(const float* __restrict__ A,
                                                         const float* __restrict__ W,
                                                         const float* __restrict__ bias,
                                                         float* __restrict__ C) {
    __shared__ uint32_t As[128][20];   // 16 half2 per row (+4 pad)
    __shared__ uint32_t Ws[128][20];
    const int bm = blockIdx.y * 128;
    const int bn = blockIdx.x * 128;
    const int tid = threadIdx.x;
    const int wid = tid >> 5, lane = tid & 31;
    const int wm = wid & 3, wn = wid >> 2;
    const int gid = lane >> 2, tig = lane & 3;

    float acc[2][8][4];
    #pragma unroll
    for (int mt = 0; mt < 2; mt++)
        #pragma unroll
        for (int nt = 0; nt < 8; nt++)
            #pragma unroll
            for (int i = 0; i < 4; i++) acc[mt][nt][i] = 0.f;

    for (int k0 = 0; k0 < 256; k0 += 32) {
        __syncthreads();
        #pragma unroll
        for (int i = tid; i < 128*16; i += 256) {
            int r = i >> 4, c2 = i & 15;
            float2 a = *(const float2*)&A[(size_t)(bm + r) * 256 + k0 + c2*2];
            float2 w = *(const float2*)&W[(size_t)(bn + r) * 256 + k0 + c2*2];
            As[r][c2] = pack_h2(a.x, a.y);
            Ws[r][c2] = pack_h2(w.x, w.y);
        }
        __syncthreads();
        #pragma unroll
        for (int ks = 0; ks < 2; ks++) {
            uint32_t afr[2][4];
            #pragma unroll
            for (int mt = 0; mt < 2; mt++) {
                int r = wm*32 + mt*16 + gid;
                int h2 = ks*8 + tig;
                afr[mt][0] = As[r][h2];       afr[mt][1] = As[r+8][h2];
                afr[mt][2] = As[r][h2 + 4];   afr[mt][3] = As[r+8][h2 + 4];
            }
            #pragma unroll
            for (int nt = 0; nt < 8; nt++) {
                int nr = wn*64 + nt*8 + gid;
                uint32_t b0 = Ws[nr][ks*8 + tig];
                uint32_t b1 = Ws[nr][ks*8 + tig + 4];
                #pragma unroll
                for (int mt = 0; mt < 2; mt++)
                    mma_f16(acc[mt][nt][0], acc[mt][nt][1], acc[mt][nt][2], acc[mt][nt][3],
                            afr[mt][0], afr[mt][1], afr[mt][2], afr[mt][3], b0, b1);
            }
        }
    }
    #pragma unroll
    for (int mt = 0; mt < 2; mt++) {
        int r = bm + wm*32 + mt*16 + gid;
        #pragma unroll
        for (int nt = 0; nt < 8; nt++) {
            int col = bn + wn*64 + nt*8 + 2*tig;
            float bv0 = bias[col], bv1 = bias[col + 1];
            float2 v0 = make_float2(acc[mt][nt][0] + bv0, acc[mt][nt][1] + bv1);
            float2 v1 = make_float2(acc[mt][nt][2] + bv0, acc[mt][nt][3] + bv1);
            *(float2*)&C[(size_t)r * 256 + col] = v0;
            *(float2*)&C[(size_t)(r + 8) * 256 + col] = v1;
        }
    }
}

// ---------------- key_global partials ----------------
__global__ __launch_bounds__(256) void kg_partial_kernel(const float* __restrict__ Kp,
                                                         const float* __restrict__ value,
                                                         float* __restrict__ kgpart) {
    __shared__ float vs[128];
    const int chunk = blockIdx.x, b = blockIdx.y;
    const int c = threadIdx.x;
    const int n0 = chunk * 128;
    if (c < 128) vs[c] = value[b*NN + n0 + c];
    __syncthreads();
    const float* kp = &Kp[(size_t)(b*NN + n0) * DD + c];
    float a0 = 0.f, a1 = 0.f, a2 = 0.f, a3 = 0.f;
    #pragma unroll 4
    for (int n = 0; n < 128; n += 4) {
        a0 += kp[(size_t)(n+0) * DD] * vs[n+0];
        a1 += kp[(size_t)(n+1) * DD] * vs[n+1];
        a2 += kp[(size_t)(n+2) * DD] * vs[n+2];
        a3 += kp[(size_t)(n+3) * DD] * vs[n+3];
    }
    kgpart[(size_t)(b*8 + chunk) * DD + c] = (a0 + a1) + (a2 + a3);
}

__global__ __launch_bounds__(256) void kg_finalize_kernel(const float* __restrict__ kgpart,
                                                          float* __restrict__ kg) {
    const int b = blockIdx.x, c = threadIdx.x;
    float s = 0.f;
    #pragma unroll
    for (int ch = 0; ch < 8; ch++) s += kgpart[(size_t)(b*8 + ch) * DD + c];
    kg[b*DD + c] = s * (1.0f / NN);
}

// ---------------- FP16 m16n8k16 flash attention with scalar V ----------------
// block: 128 queries for one (b,h); 8 warps = 4(m:32q) x 2(n:64keys); key tiles of 128
__global__ __launch_bounds__(256) void flash_mma16_kernel(const float* __restrict__ Qp,
                                                          const float* __restrict__ Kp,
                                                          const float* __restrict__ value,
                                                          float* __restrict__ parth) {
    __shared__ uint32_t Qs[128][20];   // 16 half2 per row (+4 pad)
    __shared__ uint32_t Ks[128][20];
    __shared__ float vs[128];
    __shared__ float lred[2][128];
    __shared__ float sred[2][128];
    const int b = blockIdx.z, h = blockIdx.y;
    const int q0 = blockIdx.x * 128;
    const int tid = threadIdx.x;
    const int wid = tid >> 5, lane = tid & 31;
    const int wm = wid & 3, wn = wid >> 2;
    const int gid = lane >> 2, tig = lane & 3;

    // load Q tile (128 x 32 fp32 -> 128 x 16 half2)
    {
        const float* src = &Qp[(size_t)(b*NN + q0) * DD + h * DKH];
        #pragma unroll
        for (int i = tid; i < 128*16; i += 256) {
            int r = i >> 4, c2 = i & 15;
            float2 v = *(const float2*)&src[(size_t)r * DD + c2*2];
            Qs[r][c2] = pack_h2(v.x, v.y);
        }
    }
    __syncthreads();

    // persistent A fragments: 2 m-tiles x 2 k-steps x 4 regs
    uint32_t afr[2][2][4];
    #pragma unroll
    for (int mt = 0; mt < 2; mt++)
        #pragma unroll
        for (int ks = 0; ks < 2; ks++) {
            int r = wm*32 + mt*16 + gid;
            int h2 = ks*8 + tig;
            afr[mt][ks][0] = Qs[r][h2];       afr[mt][ks][1] = Qs[r+8][h2];
            afr[mt][ks][2] = Qs[r][h2 + 4];   afr[mt][ks][3] = Qs[r+8][h2 + 4];
        }

    float la[2][2] = {{0.f,0.f},{0.f,0.f}};
    float sa[2][2] = {{0.f,0.f},{0.f,0.f}};

    for (int kt = 0; kt < NN; kt += 128) {
        __syncthreads();
        const float* ksrc = &Kp[(size_t)(b*NN + kt) * DD + h * DKH];
        #pragma unroll
        for (int i = tid; i < 128*16; i += 256) {
            int r = i >> 4, c2 = i & 15;
            float2 v = *(const float2*)&ksrc[(size_t)r * DD + c2*2];
            Ks[r][c2] = pack_h2(v.x, v.y);
        }
        if (tid < 128) vs[tid] = value[b*NN + kt + tid];
        __syncthreads();

        #pragma unroll
        for (int nt = 0; nt < 8; nt++) {
            int nb = wn*64 + nt*8;
            uint32_t bfr[2][2];
            #pragma unroll
            for (int ks = 0; ks < 2; ks++) {
                bfr[ks][0] = Ks[nb + gid][ks*8 + tig];
                bfr[ks][1] = Ks[nb + gid][ks*8 + tig + 4];
            }
            float v0 = vs[nb + 2*tig], v1 = vs[nb + 2*tig + 1];
            #pragma unroll
            for (int mt = 0; mt < 2; mt++) {
                float c0 = 0.f, c1 = 0.f, c2 = 0.f, c3 = 0.f;
                #pragma unroll
                for (int ks = 0; ks < 2; ks++)
                    mma_f16(c0, c1, c2, c3,
                            afr[mt][ks][0], afr[mt][ks][1], afr[mt][ks][2], afr[mt][ks][3],
                            bfr[ks][0], bfr[ks][1]);
                float e0 = __expf(c0 * ATTN_SCALE);
                float e1 = __expf(c1 * ATTN_SCALE);
                float e2 = __expf(c2 * ATTN_SCALE);
                float e3 = __expf(c3 * ATTN_SCALE);
                la[mt][0] += e0 + e1;  sa[mt][0] += e0*v0 + e1*v1;
                la[mt][1] += e2 + e3;  sa[mt][1] += e2*v0 + e3*v1;
            }
        }
    }

    // reduce across the 4 lanes of each quad (they share the same q row)
    #pragma unroll
    for (int mt = 0; mt < 2; mt++)
        #pragma unroll
        for (int rr = 0; rr < 2; rr++) {
            float l = la[mt][rr], s = sa[mt][rr];
            l += __shfl_xor_sync(0xffffffffu, l, 1);
            l += __shfl_xor_sync(0xffffffffu, l, 2);
            s += __shfl_xor_sync(0xffffffffu, s, 1);
            s += __shfl_xor_sync(0xffffffffu, s, 2);
            la[mt][rr] = l; sa[mt][rr] = s;
        }
    if (tig == 0) {
        #pragma unroll
        for (int mt = 0; mt < 2; mt++) {
            int r0 = wm*32 + mt*16 + gid;
            lred[wn][r0]     = la[mt][0];  sred[wn][r0]     = sa[mt][0];
            lred[wn][r0 + 8] = la[mt][1];  sred[wn][r0 + 8] = sa[mt][1];
        }
    }
    __syncthreads();
    if (tid < 128) {
        float l = lred[0][tid] + lred[1][tid];
        float s = sred[0][tid] + sred[1][tid];
        parth[(size_t)(b*NH + h) * NN + q0 + tid] = s / l;
    }
}

// ---------------- combine: f = (1-lam)*part + lam*whole -> out[:, :, 0] ----------------
__global__ __launch_bounds__(256) void combine_kernel(const float* __restrict__ Qp,
                                                      const float* __restrict__ kg,
                                                      const float* __restrict__ parth,
                                                      const float* __restrict__ lamda,
                                                      float* __restrict__ out) {
    int idx = blockIdx.x * 256 + threadIdx.x;   // b*1024+n
    int b = idx >> 10, n = idx & 1023;
    const float4* q   = (const float4*)&Qp[(size_t)idx * DD];
    const float4* kgp = (const float4*)&kg[b * DD];
    float wsum = 0.f;
    #pragma unroll
    for (int h = 0; h < NH; h++) {
        float d = 0.f;
        #pragma unroll
        for (int i = 0; i < 8; i++) {
            float4 qv = q[h*8 + i], kv = kgp[h*8 + i];
            d += qv.x*kv.x + qv.y*kv.y + qv.z*kv.z + qv.w*kv.w;
        }
        wsum += fmaxf(d * ATTN_SCALE, 0.f);
    }
    float whole = wsum * 0.125f;
    float p = 0.f;
    #pragma unroll
    for (int h = 0; h < NH; h++) p += parth[(size_t)(b*NH + h) * NN + n];
    p *= 0.125f;
    float lam = lamda[0];
    out[(size_t)idx * 8] = (1.f - lam) * p + lam * whole;
}

// ---------------- fused PMMS-1 iteration (8 chunks of 128 tokens, half-split dot) ----------------
__global__ __launch_bounds__(256) void pmms1_iter_kernel(const float* __restrict__ qT,
                                                         const float* __restrict__ query,
                                                         const float* __restrict__ mu_a,
                                                         const float* __restrict__ mupart_in,
                                                         const float* __restrict__ colpart_in,
                                                         float* __restrict__ mupart_out,
                                                         float* __restrict__ colpart_out,
                                                         int first) {
    __shared__ float mus2[256][8];        // [c][k]
    __shared__ float zpart[2][CHT][6];    // per-half partial dots
    __shared__ float zz[CHT][8];          // normalized z
    __shared__ float red[8];
    const int chunk = blockIdx.x, b = blockIdx.y;
    const int tid = threadIdx.x;

    // ---- Phase 0: materialize current mu into smem ----
    if (first) {
        for (int i = tid; i < 256 * 5; i += 256) mus2[i / 5][i % 5] = mu_a[i];
        __syncthreads();
    } else {
        const int c = tid;
        float v[5];
        #pragma unroll
        for (int k = 0; k < 5; k++) {
            float cs = 0.f, a = 0.f;
            #pragma unroll
            for (int ch = 0; ch < NCH; ch++) {
                cs += colpart_in[(b*NCH + ch) * 5 + k];
                a  += mupart_in[(size_t)((b*NCH + ch) * 5 + k) * 256 + c];
            }
            v[k] = a / (1e-6f + cs);
        }
        #pragma unroll
        for (int k = 0; k < 5; k++) {
            float s = blockReduceSum256(v[k] * v[k], red);
            mus2[c][k] = v[k] / (1e-6f + sqrtf(s));
        }
        __syncthreads();
    }

    // ---- Phase A: z for this chunk's 128 tokens; dot split across 2 threads ----
    {
        const int token = tid & (CHT - 1);
        const int half  = tid >> 7;           // 0 or 1 (c range 0-127 / 128-255)
        const int n = chunk * CHT + token;
        const float* qp = &qT[((size_t)(b*DD) + half*128) * NN + n];
        float acc[5] = {0.f, 0.f, 0.f, 0.f, 0.f};
        #pragma unroll 8
        for (int c = 0; c < 128; c++) {
            float qv = qp[(size_t)c * NN];
            float4 m4 = *(const float4*)&mus2[half*128 + c][0];
            float m5 = mus2[half*128 + c][4];
            acc[0] += qv * m4.x; acc[1] += qv * m4.y; acc[2] += qv * m4.z;
            acc[3] += qv * m4.w; acc[4] += qv * m5;
        }
        #pragma unroll
        for (int k = 0; k < 5; k++) zpart[half][token][k] = acc[k];
        __syncthreads();

        float z[5] = {0.f, 0.f, 0.f, 0.f, 0.f};
        if (tid < CHT) {
            float s[5];
            #pragma unroll
            for (int k = 0; k < 5; k++) s[k] = zpart[0][tid][k] + zpart[1][tid][k];
            float m = s[0];
            #pragma unroll
            for (int k = 1; k < 5; k++) m = fmaxf(m, s[k]);
            float sum = 0.f;
            #pragma unroll
            for (int k = 0; k < 5; k++) { z[k] = __expf(20.f * (s[k] - m)); sum += z[k]; }
            float inv = 1.f / sum;
            #pragma unroll
            for (int k = 0; k < 5; k++) { z[k] *= inv; zz[tid][k] = z[k]; }
        }
        #pragma unroll
        for (int k = 0; k < 5; k++) {
            float s = blockReduceSum256(z[k], red);
            if (tid == 0) colpart_out[(b*NCH + chunk) * 5 + k] = s;
        }
    }

    // ---- Phase B: mu partials (thread = channel, 128 tokens) ----
    {
        const int c = tid;
        const float* qb = &query[(size_t)(b*NN + chunk*CHT) * DD + c];
        float acc[5] = {0.f, 0.f, 0.f, 0.f, 0.f};
        #pragma unroll 8
        for (int n = 0; n < CHT; n++) {
            float qv = qb[(size_t)n * DD];
            float4 z4 = *(const float4*)&zz[n][0];
            float z5 = zz[n][4];
            acc[0] += qv * z4.x; acc[1] += qv * z4.y; acc[2] += qv * z4.z;
            acc[3] += qv * z4.w; acc[4] += qv * z5;
        }
        #pragma unroll
        for (int k = 0; k < 5; k++)
            mupart_out[(size_t)((b*NCH + chunk) * 5 + k) * 256 + c] = acc[k];
    }
}

// ---------------- PMMS mu finalize: sum chunks, /colsum, l2norm over c ----------------
template<int K>
__global__ __launch_bounds__(256) void mustep_finalize(const float* __restrict__ mupart,
                                                       const float* __restrict__ colpart,
                                                       float* __restrict__ mu) {
    __shared__ float red[8];
    const int b = blockIdx.x, c = threadIdx.x;
    float acc[K];
    #pragma unroll
    for (int k = 0; k < K; k++) {
        float cs = 0.f, a = 0.f;
        #pragma unroll
        for (int ch = 0; ch < NCH; ch++) {
            cs += colpart[(b*NCH + ch) * K + k];
            a  += mupart[(size_t)((b*NCH + ch) * K + k) * 256 + c];
        }
        acc[k] = a / (1e-6f + cs);
    }
    #pragma unroll
    for (int k = 0; k < K; k++) {
        float s = blockReduceSum256(acc[k] * acc[k], red);
        acc[k] = acc[k] / (1e-6f + sqrtf(s));
    }
    #pragma unroll
    for (int k = 0; k < K; k++) mu[(b*256 + c) * K + k] = acc[k];
}

// ---------------- P = softmax(query @ mu), kappa=1, chunked + half-split ----------------
template<int K>
__global__ __launch_bounds__(256) void zstepT_kernel(const float* __restrict__ qT,
                                                     const float* __restrict__ mu,
                                                     float* __restrict__ P) {
    __shared__ float mus2[256][8];
    __shared__ float zpart[2][CHT][6];
    const int b = blockIdx.y, tid = threadIdx.x;
    for (int i = tid; i < 256 * K; i += 256) mus2[i / K][i % K] = mu[(b*256) * K + i];
    __syncthreads();
    const int token = tid & (CHT - 1);
    const int half  = tid >> 7;
    const int n = blockIdx.x * CHT + token;
    const float* qp = &qT[((size_t)(b*DD) + half*128) * NN + n];
    float acc[K];
    #pragma unroll
    for (int k = 0; k < K; k++) acc[k] = 0.f;
    #pragma unroll 8
    for (int c = 0; c < 128; c++) {
        float qv = qp[(size_t)c * NN];
        #pragma unroll
        for (int k = 0; k < K; k++) acc[k] += qv * mus2[half*128 + c][k];
    }
    #pragma unroll
    for (int k = 0; k < K; k++) zpart[half][token][k] = acc[k];
    __syncthreads();
    if (tid < CHT) {
        float s[K];
        #pragma unroll
        for (int k = 0; k < K; k++) s[k] = zpart[0][tid][k] + zpart[1][tid][k];
        float m = s[0];
        #pragma unroll
        for (int k = 1; k < K; k++) m = fmaxf(m, s[k]);
        float sum = 0.f;
        #pragma unroll
        for (int k = 0; k < K; k++) { s[k] = __expf(s[k] - m); sum += s[k]; }
        float inv = 1.f / sum;
        #pragma unroll
        for (int k = 0; k < K; k++) P[(size_t)(b*NN + n) * K + k] = s[k] * inv;
    }
}

// ---------------- PMMS-2: node = mu1 (b,256,5), 10 iterations fully in-block ----------------
__global__ __launch_bounds__(256) void pmms2_kernel(const float* __restrict__ mu1,
                                                    const float* __restrict__ mu_b,
                                                    float* __restrict__ mu2) {
    const int b = blockIdx.x, c = threadIdx.x;
    __shared__ float node[256][5];
    __shared__ float zsh[5][2];
    __shared__ float Ssh[10];
    __shared__ float red[8];
    #pragma unroll
    for (int n = 0; n < 5; n++) node[c][n] = mu1[(b*256 + c) * 5 + n];
    float mk0 = mu_b[c*2 + 0], mk1 = mu_b[c*2 + 1];

    for (int it = 0; it < 10; it++) {
        #pragma unroll
        for (int j = 0; j < 10; j++) {
            int n = j >> 1, k = j & 1;
            float v = node[c][n] * (k ? mk1 : mk0);
            float s = blockReduceSum256(v, red);
            if (c == 0) Ssh[j] = s;
        }
        __syncthreads();
        if (c == 0) {
            float csum0 = 0.f, csum1 = 0.f;
            float zt[5][2];
            #pragma unroll
            for (int n = 0; n < 5; n++) {
                float a = 20.f * Ssh[n*2 + 0];
                float q = 20.f * Ssh[n*2 + 1];
                float m = fmaxf(a, q);
                float ea = __expf(a - m), eb = __expf(q - m);
                float inv = 1.f / (ea + eb);
                zt[n][0] = ea * inv; zt[n][1] = eb * inv;
                csum0 += zt[n][0];   csum1 += zt[n][1];
            }
            #pragma unroll
            for (int n = 0; n < 5; n++) {
                zsh[n][0] = zt[n][0] / (1e-6f + csum0);
                zsh[n][1] = zt[n][1] / (1e-6f + csum1);
            }
        }
        __syncthreads();
        float nk0 = 0.f, nk1 = 0.f;
        #pragma unroll
        for (int n = 0; n < 5; n++) {
            nk0 += node[c][n] * zsh[n][0];
            nk1 += node[c][n] * zsh[n][1];
        }
        float s0 = blockReduceSum256(nk0 * nk0, red);
        float s1 = blockReduceSum256(nk1 * nk1, red);
        mk0 = nk0 / (1e-6f + sqrtf(s0));
        mk1 = nk1 / (1e-6f + sqrtf(s1));
        __syncthreads();
    }
    mu2[(b*256 + c) * 2 + 0] = mk0;
    mu2[(b*256 + c) * 2 + 1] = mk1;
}

// ---------------- node_weight: conv(1->16)+BN+ReLU+conv(16->1)+sigmoid gating ----------------
__global__ __launch_bounds__(1024) void nw_kernel(const float* __restrict__ P, int CH,
                                                  const float* __restrict__ w1,
                                                  const float* __restrict__ b1,
                                                  const float* __restrict__ g,
                                                  const float* __restrict__ be,
                                                  const float* __restrict__ w2,
                                                  const float* __restrict__ b2,
                                                  float* __restrict__ out, int outOff) {
    __shared__ float img[34][34];
    __shared__ float t1[8][34][34];
    __shared__ float sw1[144], sw2[144], sb1[16], sg[16], sbe[16];
    const int blk = blockIdx.x;
    const int b = blk / CH, ch = blk % CH;
    const int t = threadIdx.x;
    const int r = t >> 5, c = t & 31;

    for (int i = t; i < 34*34; i += 1024) ((float*)img)[i] = 0.f;
    for (int i = t; i < 8*34*34; i += 1024) ((float*)t1)[i] = 0.f;
    const float bninv = rsqrtf(1.f + 1e-5f);
    if (t < 144) { sw1[t] = w1[t]; sw2[t] = w2[t]; }
    if (t < 16)  { sb1[t] = b1[t]; sg[t] = g[t] * bninv; sbe[t] = be[t]; }
    __syncthreads();

    const int n = r * 32 + c;
    float xv = P[(size_t)((b << 10) + n) * CH + ch];
    img[r + 1][c + 1] = xv;
    float acc = b2[0];

    for (int half = 0; half < 2; half++) {
        __syncthreads();
        #pragma unroll
        for (int oc = 0; oc < 8; oc++) {
            int o = half * 8 + oc;
            float v = sb1[o];
            #pragma unroll
            for (int dy = 0; dy < 3; dy++)
                #pragma unroll
                for (int dx = 0; dx < 3; dx++)
                    v += sw1[o*9 + dy*3 + dx] * img[r + dy][c + dx];
            v = fmaxf(v * sg[o] + sbe[o], 0.f);
            t1[oc][r + 1][c + 1] = v;
        }
        __syncthreads();
        #pragma unroll
        for (int ic = 0; ic < 8; ic++) {
            int i2 = half * 8 + ic;
            #pragma unroll
            for (int dy = 0; dy < 3; dy++)
                #pragma unroll
                for (int dx = 0; dx < 3; dx++)
                    acc += sw2[i2*9 + dy*3 + dx] * t1[ic][r + dy][c + dx];
        }
    }
    float y = 1.f / (1.f + __expf(-acc));
    out[(size_t)((b << 10) + n) * 8 + outOff + ch] = xv * y;
}

// ---------------- launch ----------------
extern "C" void kernel_launch(void* const* d_in, const int* in_sizes, int n_in,
                              void* d_out, int out_size) {
    const float* query = (const float*)d_in[0];
    const float* key   = (const float*)d_in[1];
    const float* value = (const float*)d_in[2];
    const float* lamda = (const float*)d_in[3];
    const float* W0    = (const float*)d_in[4];
    const float* b0    = (const float*)d_in[5];
    const float* W1    = (const float*)d_in[6];
    const float* b1    = (const float*)d_in[7];
    const float* mu_a  = (const float*)d_in[8];
    const float* mu_b  = (const float*)d_in[9];
    const float* nw1_w1 = (const float*)d_in[10];
    const float* nw1_b1 = (const float*)d_in[11];
    const float* nw1_g  = (const float*)d_in[12];
    const float* nw1_be = (const float*)d_in[13];
    const float* nw1_w2 = (const float*)d_in[14];
    const float* nw1_b2 = (const float*)d_in[15];
    const float* nw2_w1 = (const float*)d_in[16];
    const float* nw2_b1 = (const float*)d_in[17];
    const float* nw2_g  = (const float*)d_in[18];
    const float* nw2_be = (const float*)d_in[19];
    const float* nw2_w2 = (const float*)d_in[20];
    const float* nw2_b2 = (const float*)d_in[21];
    float* out = (float*)d_out;

    float *Qp, *Kp, *qT, *kg, *kgpart, *parth, *mu1, *mu2, *P1, *P2;
    float *colpart, *mupart;
    cudaGetSymbolAddress((void**)&Qp, g_Qp);
    cudaGetSymbolAddress((void**)&Kp, g_Kp);
    cudaGetSymbolAddress((void**)&qT, g_qT);
    cudaGetSymbolAddress((void**)&kg, g_kg);
    cudaGetSymbolAddress((void**)&kgpart, g_kgpart);
    cudaGetSymbolAddress((void**)&parth, g_parth);
    cudaGetSymbolAddress((void**)&mu1, g_mu1);
    cudaGetSymbolAddress((void**)&mu2, g_mu2);
    cudaGetSymbolAddress((void**)&colpart, g_colpart);
    cudaGetSymbolAddress((void**)&mupart, g_mupart);
    cudaGetSymbolAddress((void**)&P1, g_P1);
    cudaGetSymbolAddress((void**)&P2, g_P2);

    float* mp[2] = {mupart, mupart + BB*NCH*5*DD};
    float* cp[2] = {colpart, colpart + BB*NCH*5};

    // Transpose query for coalesced PMMS access
    transpose_kernel<<<dim3(32, 8, 16), dim3(32, 8)>>>(query, qT);

    // Projections (fp16 tensor-core MMA, fp32 accumulate)
    proj_mma16_kernel<<<dim3(2, 128), 256>>>(query, W0, b0, Qp);
    proj_mma16_kernel<<<dim3(2, 128), 256>>>(key,   W1, b1, Kp);

    // Attention
    kg_partial_kernel<<<dim3(8, BB), 256>>>(Kp, value, kgpart);
    kg_finalize_kernel<<<BB, 256>>>(kgpart, kg);
    flash_mma16_kernel<<<dim3(8, NH, BB), 256>>>(Qp, Kp, value, parth);
    combine_kernel<<<64, 256>>>(Qp, kg, parth, lamda, out);

    // PMMS-1 (K=5, 10 fused iterations, ping-pong partials, 8 chunks)
    for (int it = 0; it < 10; it++) {
        int ob = it & 1;
        int ib = ob ^ 1;
        pmms1_iter_kernel<<<dim3(NCH, BB), 256>>>(qT, query, mu_a,
                                                  mp[ib], cp[ib], mp[ob], cp[ob],
                                                  it == 0 ? 1 : 0);
    }
    mustep_finalize<5><<<BB, 256>>>(mp[1], cp[1], mu1);   // iter 9 wrote buffer 1

    // P1 = softmax(query @ mu1)
    zstepT_kernel<5><<<dim3(NCH, BB), 256>>>(qT, mu1, P1);

    // PMMS-2 (node = mu1, K=2)
    pmms2_kernel<<<BB, 256>>>(mu1, mu_b, mu2);
    zstepT_kernel<2><<<dim3(NCH, BB), 256>>>(qT, mu2, P2);

    // node_weight gating
    nw_kernel<<<BB * 5, 1024>>>(P1, 5, nw1_w1, nw1_b1, nw1_g, nw1_be, nw1_w2, nw1_b2, out, 1);
    nw_kernel<<<BB * 2, 1024>>>(P2, 2, nw2_w1, nw2_b1, nw2_g, nw2_be, nw2_w2, nw2_b2, out, 6);
}

// round 16
// speedup vs baseline: 2.6090x; 1.1308x over previous
#include <cuda_runtime.h>
#include <cuda_fp16.h>
#include <cstdint>
#include <math.h>

#define BB 16
#define NN 1024
#define DD 256
#define NH 8
#define DKH 32
#define NCH 8     // PMMS chunks per batch
#define CHT 128   // tokens per chunk
#define ATTN_SCALE 0.17677669529663687f  // 1/sqrt(32)

// ---------------- scratch (static device globals; no allocation) ----------------
__device__ float g_Qp[BB*NN*DD];       // 16 MB
__device__ float g_Kp[BB*NN*DD];       // 16 MB
__device__ float g_qT[BB*DD*NN];       // 16 MB  (query transposed: [b][c][n])
__device__ float g_kg[BB*DD];
__device__ float g_kgpart[BB*8*DD];
__device__ float g_parth[BB*NH*NN];
__device__ float g_mu1[BB*DD*5];
__device__ float g_mu2[BB*DD*2];
__device__ float g_colpart[2][BB*NCH*5];
__device__ float g_mupart[2][BB*NCH*5*DD];
__device__ float g_P1[BB*NN*5];
__device__ float g_P2[BB*NN*2];

// ---------------- helpers ----------------
__device__ __forceinline__ float blockReduceSum256(float v, float* red) {
    #pragma unroll
    for (int off = 16; off; off >>= 1) v += __shfl_down_sync(0xffffffffu, v, off);
    int w = threadIdx.x >> 5;
    if ((threadIdx.x & 31) == 0) red[w] = v;
    __syncthreads();
    if (threadIdx.x < 32) {
        float r = (threadIdx.x < 8) ? red[threadIdx.x] : 0.f;
        #pragma unroll
        for (int off = 4; off; off >>= 1) r += __shfl_down_sync(0xffffffffu, r, off);
        if (threadIdx.x == 0) red[0] = r;
    }
    __syncthreads();
    float out = red[0];
    __syncthreads();
    return out;
}

// 512-thread block reduction; ALL threads must call (idle lanes pass 0)
__device__ __forceinline__ float blockReduceSum512(float v, float* red) {
    #pragma unroll
    for (int off = 16; off; off >>= 1) v += __shfl_down_sync(0xffffffffu, v, off);
    int w = threadIdx.x >> 5;
    if ((threadIdx.x & 31) == 0) red[w] = v;
    __syncthreads();
    if (threadIdx.x < 32) {
        float r = (threadIdx.x < 16) ? red[threadIdx.x] : 0.f;
        #pragma unroll
        for (int off = 8; off; off >>= 1) r += __shfl_down_sync(0xffffffffu, r, off);
        if (threadIdx.x == 0) red[0] = r;
    }
    __syncthreads();
    float out = red[0];
    __syncthreads();
    return out;
}

__device__ __forceinline__ uint32_t pack_h2(float a, float b) {
    __half2 h = __floats2half2_rn(a, b);
    return *(uint32_t*)&h;
}

__device__ __forceinline__ void mma_f16(float& c0, float& c1, float& c2, float& c3,
                                        uint32_t a0, uint32_t a1, uint32_t a2, uint32_t a3,
                                        uint32_t b0, uint32_t b1) {
    asm("mma.sync.aligned.m16n8k16.row.col.f32.f16.f16.f32 "
        "{%0,%1,%2,%3}, {%4,%5,%6,%7}, {%8,%9}, {%0,%1,%2,%3};"
        : "+f"(c0), "+f"(c1), "+f"(c2), "+f"(c3)
        : "r"(a0), "r"(a1), "r"(a2), "r"(a3), "r"(b0), "r"(b1));
}

// ---------------- transpose: qT[b][c][n] = query[b][n][c] ----------------
__global__ __launch_bounds__(256) void transpose_kernel(const float* __restrict__ q,
                                                        float* __restrict__ qT) {
    __shared__ float tile[32][33];
    const int b = blockIdx.z;
    const int n0 = blockIdx.x * 32;
    const int c0 = blockIdx.y * 32;
    const int tx = threadIdx.x, ty = threadIdx.y;
    #pragma unroll
    for (int j = 0; j < 4; j++)
        tile[ty + 8*j][tx] = q[(size_t)(b*NN + n0 + ty + 8*j) * DD + c0 + tx];
    __syncthreads();
    #pragma unroll
    for (int j = 0; j < 4; j++)
        qT[(size_t)(b*DD + c0 + ty + 8*j) * NN + n0 + tx] = tile[tx][ty + 8*j];
}

// ---------------- FP16 MMA projection GEMM: C[16384,256] = A @ W^T + bias ----------------
__global__ __launch_bounds__(256) void proj_mma16_kernel(const float* __restrict__ A,
                                                         const float* __restrict__ W,
                                                         const float* __restrict__ bias,
                                                         float* __restrict__ C) {
    __shared__ uint32_t As[128][20];   // 16 half2 per row (+4 pad)
    __shared__ uint32_t Ws[128][20];
    const int bm = blockIdx.y * 128;
    const int bn = blockIdx.x * 128;
    const int tid = threadIdx.x;
    const int wid = tid >> 5, lane = tid & 31;
    const int wm = wid & 3, wn = wid >> 2;
    const int gid = lane >> 2, tig = lane & 3;

    float acc[2][8][4];
    #pragma unroll
    for (int mt = 0; mt < 2; mt++)
        #pragma unroll
        for (int nt = 0; nt < 8; nt++)
            #pragma unroll
            for (int i = 0; i < 4; i++) acc[mt][nt][i] = 0.f;

    for (int k0 = 0; k0 < 256; k0 += 32) {
        __syncthreads();
        #pragma unroll
        for (int i = tid; i < 128*16; i += 256) {
            int r = i >> 4, c2 = i & 15;
            float2 a = *(const float2*)&A[(size_t)(bm + r) * 256 + k0 + c2*2];
            float2 w = *(const float2*)&W[(size_t)(bn + r) * 256 + k0 + c2*2];
            As[r][c2] = pack_h2(a.x, a.y);
            Ws[r][c2] = pack_h2(w.x, w.y);
        }
        __syncthreads();
        #pragma unroll
        for (int ks = 0; ks < 2; ks++) {
            uint32_t afr[2][4];
            #pragma unroll
            for (int mt = 0; mt < 2; mt++) {
                int r = wm*32 + mt*16 + gid;
                int h2 = ks*8 + tig;
                afr[mt][0] = As[r][h2];       afr[mt][1] = As[r+8][h2];
                afr[mt][2] = As[r][h2 + 4];   afr[mt][3] = As[r+8][h2 + 4];
            }
            #pragma unroll
            for (int nt = 0; nt < 8; nt++) {
                int nr = wn*64 + nt*8 + gid;
                uint32_t b0 = Ws[nr][ks*8 + tig];
                uint32_t b1 = Ws[nr][ks*8 + tig + 4];
                #pragma unroll
                for (int mt = 0; mt < 2; mt++)
                    mma_f16(acc[mt][nt][0], acc[mt][nt][1], acc[mt][nt][2], acc[mt][nt][3],
                            afr[mt][0], afr[mt][1], afr[mt][2], afr[mt][3], b0, b1);
            }
        }
    }
    #pragma unroll
    for (int mt = 0; mt < 2; mt++) {
        int r = bm + wm*32 + mt*16 + gid;
        #pragma unroll
        for (int nt = 0; nt < 8; nt++) {
            int col = bn + wn*64 + nt*8 + 2*tig;
            float bv0 = bias[col], bv1 = bias[col + 1];
            float2 v0 = make_float2(acc[mt][nt][0] + bv0, acc[mt][nt][1] + bv1);
            float2 v1 = make_float2(acc[mt][nt][2] + bv0, acc[mt][nt][3] + bv1);
            *(float2*)&C[(size_t)r * 256 + col] = v0;
            *(float2*)&C[(size_t)(r + 8) * 256 + col] = v1;
        }
    }
}

// ---------------- key_global partials ----------------
__global__ __launch_bounds__(256) void kg_partial_kernel(const float* __restrict__ Kp,
                                                         const float* __restrict__ value,
                                                         float* __restrict__ kgpart) {
    __shared__ float vs[128];
    const int chunk = blockIdx.x, b = blockIdx.y;
    const int c = threadIdx.x;
    const int n0 = chunk * 128;
    if (c < 128) vs[c] = value[b*NN + n0 + c];
    __syncthreads();
    const float* kp = &Kp[(size_t)(b*NN + n0) * DD + c];
    float a0 = 0.f, a1 = 0.f, a2 = 0.f, a3 = 0.f;
    #pragma unroll 4
    for (int n = 0; n < 128; n += 4) {
        a0 += kp[(size_t)(n+0) * DD] * vs[n+0];
        a1 += kp[(size_t)(n+1) * DD] * vs[n+1];
        a2 += kp[(size_t)(n+2) * DD] * vs[n+2];
        a3 += kp[(size_t)(n+3) * DD] * vs[n+3];
    }
    kgpart[(size_t)(b*8 + chunk) * DD + c] = (a0 + a1) + (a2 + a3);
}

__global__ __launch_bounds__(256) void kg_finalize_kernel(const float* __restrict__ kgpart,
                                                          float* __restrict__ kg) {
    const int b = blockIdx.x, c = threadIdx.x;
    float s = 0.f;
    #pragma unroll
    for (int ch = 0; ch < 8; ch++) s += kgpart[(size_t)(b*8 + ch) * DD + c];
    kg[b*DD + c] = s * (1.0f / NN);
}

// ---------------- FP16 m16n8k16 flash attention with scalar V ----------------
__global__ __launch_bounds__(256) void flash_mma16_kernel(const float* __restrict__ Qp,
                                                          const float* __restrict__ Kp,
                                                          const float* __restrict__ value,
                                                          float* __restrict__ parth) {
    __shared__ uint32_t Qs[128][20];   // 16 half2 per row (+4 pad)
    __shared__ uint32_t Ks[128][20];
    __shared__ float vs[128];
    __shared__ float lred[2][128];
    __shared__ float sred[2][128];
    const int b = blockIdx.z, h = blockIdx.y;
    const int q0 = blockIdx.x * 128;
    const int tid = threadIdx.x;
    const int wid = tid >> 5, lane = tid & 31;
    const int wm = wid & 3, wn = wid >> 2;
    const int gid = lane >> 2, tig = lane & 3;

    {
        const float* src = &Qp[(size_t)(b*NN + q0) * DD + h * DKH];
        #pragma unroll
        for (int i = tid; i < 128*16; i += 256) {
            int r = i >> 4, c2 = i & 15;
            float2 v = *(const float2*)&src[(size_t)r * DD + c2*2];
            Qs[r][c2] = pack_h2(v.x, v.y);
        }
    }
    __syncthreads();

    uint32_t afr[2][2][4];
    #pragma unroll
    for (int mt = 0; mt < 2; mt++)
        #pragma unroll
        for (int ks = 0; ks < 2; ks++) {
            int r = wm*32 + mt*16 + gid;
            int h2 = ks*8 + tig;
            afr[mt][ks][0] = Qs[r][h2];       afr[mt][ks][1] = Qs[r+8][h2];
            afr[mt][ks][2] = Qs[r][h2 + 4];   afr[mt][ks][3] = Qs[r+8][h2 + 4];
        }

    float la[2][2] = {{0.f,0.f},{0.f,0.f}};
    float sa[2][2] = {{0.f,0.f},{0.f,0.f}};

    for (int kt = 0; kt < NN; kt += 128) {
        __syncthreads();
        const float* ksrc = &Kp[(size_t)(b*NN + kt) * DD + h * DKH];
        #pragma unroll
        for (int i = tid; i < 128*16; i += 256) {
            int r = i >> 4, c2 = i & 15;
            float2 v = *(const float2*)&ksrc[(size_t)r * DD + c2*2];
            Ks[r][c2] = pack_h2(v.x, v.y);
        }
        if (tid < 128) vs[tid] = value[b*NN + kt + tid];
        __syncthreads();

        #pragma unroll
        for (int nt = 0; nt < 8; nt++) {
            int nb = wn*64 + nt*8;
            uint32_t bfr[2][2];
            #pragma unroll
            for (int ks = 0; ks < 2; ks++) {
                bfr[ks][0] = Ks[nb + gid][ks*8 + tig];
                bfr[ks][1] = Ks[nb + gid][ks*8 + tig + 4];
            }
            float v0 = vs[nb + 2*tig], v1 = vs[nb + 2*tig + 1];
            #pragma unroll
            for (int mt = 0; mt < 2; mt++) {
                float c0 = 0.f, c1 = 0.f, c2 = 0.f, c3 = 0.f;
                #pragma unroll
                for (int ks = 0; ks < 2; ks++)
                    mma_f16(c0, c1, c2, c3,
                            afr[mt][ks][0], afr[mt][ks][1], afr[mt][ks][2], afr[mt][ks][3],
                            bfr[ks][0], bfr[ks][1]);
                float e0 = __expf(c0 * ATTN_SCALE);
                float e1 = __expf(c1 * ATTN_SCALE);
                float e2 = __expf(c2 * ATTN_SCALE);
                float e3 = __expf(c3 * ATTN_SCALE);
                la[mt][0] += e0 + e1;  sa[mt][0] += e0*v0 + e1*v1;
                la[mt][1] += e2 + e3;  sa[mt][1] += e2*v0 + e3*v1;
            }
        }
    }

    #pragma unroll
    for (int mt = 0; mt < 2; mt++)
        #pragma unroll
        for (int rr = 0; rr < 2; rr++) {
            float l = la[mt][rr], s = sa[mt][rr];
            l += __shfl_xor_sync(0xffffffffu, l, 1);
            l += __shfl_xor_sync(0xffffffffu, l, 2);
            s += __shfl_xor_sync(0xffffffffu, s, 1);
            s += __shfl_xor_sync(0xffffffffu, s, 2);
            la[mt][rr] = l; sa[mt][rr] = s;
        }
    if (tig == 0) {
        #pragma unroll
        for (int mt = 0; mt < 2; mt++) {
            int r0 = wm*32 + mt*16 + gid;
            lred[wn][r0]     = la[mt][0];  sred[wn][r0]     = sa[mt][0];
            lred[wn][r0 + 8] = la[mt][1];  sred[wn][r0 + 8] = sa[mt][1];
        }
    }
    __syncthreads();
    if (tid < 128) {
        float l = lred[0][tid] + lred[1][tid];
        float s = sred[0][tid] + sred[1][tid];
        parth[(size_t)(b*NH + h) * NN + q0 + tid] = s / l;
    }
}

// ---------------- combine: f = (1-lam)*part + lam*whole -> out[:, :, 0] ----------------
__global__ __launch_bounds__(256) void combine_kernel(const float* __restrict__ Qp,
                                                      const float* __restrict__ kg,
                                                      const float* __restrict__ parth,
                                                      const float* __restrict__ lamda,
                                                      float* __restrict__ out) {
    int idx = blockIdx.x * 256 + threadIdx.x;   // b*1024+n
    int b = idx >> 10, n = idx & 1023;
    const float4* q   = (const float4*)&Qp[(size_t)idx * DD];
    const float4* kgp = (const float4*)&kg[b * DD];
    float wsum = 0.f;
    #pragma unroll
    for (int h = 0; h < NH; h++) {
        float d = 0.f;
        #pragma unroll
        for (int i = 0; i < 8; i++) {
            float4 qv = q[h*8 + i], kv = kgp[h*8 + i];
            d += qv.x*kv.x + qv.y*kv.y + qv.z*kv.z + qv.w*kv.w;
        }
        wsum += fmaxf(d * ATTN_SCALE, 0.f);
    }
    float whole = wsum * 0.125f;
    float p = 0.f;
    #pragma unroll
    for (int h = 0; h < NH; h++) p += parth[(size_t)(b*NH + h) * NN + n];
    p *= 0.125f;
    float lam = lamda[0];
    out[(size_t)idx * 8] = (1.f - lam) * p + lam * whole;
}

// ---------------- fused PMMS-1 iteration: 512 threads, 4-way A split, 2-way B split ----------------
__global__ __launch_bounds__(512) void pmms1_iter_kernel(const float* __restrict__ qT,
                                                         const float* __restrict__ query,
                                                         const float* __restrict__ mu_a,
                                                         const float* __restrict__ mupart_in,
                                                         const float* __restrict__ colpart_in,
                                                         float* __restrict__ mupart_out,
                                                         float* __restrict__ colpart_out,
                                                         int first) {
    __shared__ float mus2[256][8];        // [c][k]
    __shared__ float zpart[4][CHT][6];    // per-quarter partial dots
    __shared__ float zz[CHT][8];          // normalized z
    __shared__ float bpart[2][256][6];    // Phase-B token-half partials
    __shared__ float red[16];
    const int chunk = blockIdx.x, b = blockIdx.y;
    const int tid = threadIdx.x;

    // ---- Phase 0: materialize current mu into smem ----
    if (first) {
        for (int i = tid; i < 256 * 5; i += 512) mus2[i / 5][i % 5] = mu_a[i];
        __syncthreads();
    } else {
        float v[5] = {0.f, 0.f, 0.f, 0.f, 0.f};
        if (tid < 256) {
            const int c = tid;
            #pragma unroll
            for (int k = 0; k < 5; k++) {
                float cs = 0.f, a = 0.f;
                #pragma unroll
                for (int ch = 0; ch < NCH; ch++) {
                    cs += colpart_in[(b*NCH + ch) * 5 + k];
                    a  += mupart_in[(size_t)((b*NCH + ch) * 5 + k) * 256 + c];
                }
                v[k] = a / (1e-6f + cs);
            }
        }
        #pragma unroll
        for (int k = 0; k < 5; k++) {
            float s = blockReduceSum512(v[k] * v[k], red);
            if (tid < 256) mus2[tid][k] = v[k] / (1e-6f + sqrtf(s));
        }
        __syncthreads();
    }

    // ---- Phase A: z for this chunk's 128 tokens; dot split across 4 threads ----
    {
        const int token = tid & (CHT - 1);
        const int quarter = tid >> 7;         // 0..3 (c range 64*quarter .. +63)
        const int n = chunk * CHT + token;
        const float* qp = &qT[((size_t)(b*DD) + quarter*64) * NN + n];
        float acc[5] = {0.f, 0.f, 0.f, 0.f, 0.f};
        #pragma unroll 8
        for (int c = 0; c < 64; c++) {
            float qv = qp[(size_t)c * NN];
            float4 m4 = *(const float4*)&mus2[quarter*64 + c][0];
            float m5 = mus2[quarter*64 + c][4];
            acc[0] += qv * m4.x; acc[1] += qv * m4.y; acc[2] += qv * m4.z;
            acc[3] += qv * m4.w; acc[4] += qv * m5;
        }
        #pragma unroll
        for (int k = 0; k < 5; k++) zpart[quarter][token][k] = acc[k];
        __syncthreads();

        float z[5] = {0.f, 0.f, 0.f, 0.f, 0.f};
        if (tid < CHT) {
            float s[5];
            #pragma unroll
            for (int k = 0; k < 5; k++)
                s[k] = (zpart[0][tid][k] + zpart[1][tid][k]) +
                       (zpart[2][tid][k] + zpart[3][tid][k]);
            float m = s[0];
            #pragma unroll
            for (int k = 1; k < 5; k++) m = fmaxf(m, s[k]);
            float sum = 0.f;
            #pragma unroll
            for (int k = 0; k < 5; k++) { z[k] = __expf(20.f * (s[k] - m)); sum += z[k]; }
            float inv = 1.f / sum;
            #pragma unroll
            for (int k = 0; k < 5; k++) { z[k] *= inv; zz[tid][k] = z[k]; }
        }
        #pragma unroll
        for (int k = 0; k < 5; k++) {
            float s = blockReduceSum512(z[k], red);
            if (tid == 0) colpart_out[(b*NCH + chunk) * 5 + k] = s;
        }
    }

    // ---- Phase B: mu partials; 2-way token split (thread = (c, token-half)) ----
    {
        const int c = tid & 255;
        const int th = tid >> 8;              // 0 or 1 (tokens 0-63 / 64-127)
        const float* qb = &query[(size_t)(b*NN + chunk*CHT + th*64) * DD + c];
        float acc[5] = {0.f, 0.f, 0.f, 0.f, 0.f};
        #pragma unroll 8
        for (int n = 0; n < 64; n++) {
            float qv = qb[(size_t)n * DD];
            float4 z4 = *(const float4*)&zz[th*64 + n][0];
            float z5 = zz[th*64 + n][4];
            acc[0] += qv * z4.x; acc[1] += qv * z4.y; acc[2] += qv * z4.z;
            acc[3] += qv * z4.w; acc[4] += qv * z5;
        }
        #pragma unroll
        for (int k = 0; k < 5; k++) bpart[th][c][k] = acc[k];
        __syncthreads();
        if (tid < 256) {
            #pragma unroll
            for (int k = 0; k < 5; k++)
                mupart_out[(size_t)((b*NCH + chunk) * 5 + k) * 256 + tid] =
                    bpart[0][tid][k] + bpart[1][tid][k];
        }
    }
}

// ---------------- PMMS mu finalize: sum chunks, /colsum, l2norm over c ----------------
template<int K>
__global__ __launch_bounds__(256) void mustep_finalize(const float* __restrict__ mupart,
                                                       const float* __restrict__ colpart,
                                                       float* __restrict__ mu) {
    __shared__ float red[8];
    const int b = blockIdx.x, c = threadIdx.x;
    float acc[K];
    #pragma unroll
    for (int k = 0; k < K; k++) {
        float cs = 0.f, a = 0.f;
        #pragma unroll
        for (int ch = 0; ch < NCH; ch++) {
            cs += colpart[(b*NCH + ch) * K + k];
            a  += mupart[(size_t)((b*NCH + ch) * K + k) * 256 + c];
        }
        acc[k] = a / (1e-6f + cs);
    }
    #pragma unroll
    for (int k = 0; k < K; k++) {
        float s = blockReduceSum256(acc[k] * acc[k], red);
        acc[k] = acc[k] / (1e-6f + sqrtf(s));
    }
    #pragma unroll
    for (int k = 0; k < K; k++) mu[(b*256 + c) * K + k] = acc[k];
}

// ---------------- P = softmax(query @ mu), kappa=1, 512 threads, 4-way split ----------------
template<int K>
__global__ __launch_bounds__(512) void zstepT_kernel(const float* __restrict__ qT,
                                                     const float* __restrict__ mu,
                                                     float* __restrict__ P) {
    __shared__ float mus2[256][8];
    __shared__ float zpart[4][CHT][6];
    const int b = blockIdx.y, tid = threadIdx.x;
    for (int i = tid; i < 256 * K; i += 512) mus2[i / K][i % K] = mu[(b*256) * K + i];
    __syncthreads();
    const int token = tid & (CHT - 1);
    const int quarter = tid >> 7;
    const int n = blockIdx.x * CHT + token;
    const float* qp = &qT[((size_t)(b*DD) + quarter*64) * NN + n];
    float acc[K];
    #pragma unroll
    for (int k = 0; k < K; k++) acc[k] = 0.f;
    #pragma unroll 8
    for (int c = 0; c < 64; c++) {
        float qv = qp[(size_t)c * NN];
        #pragma unroll
        for (int k = 0; k < K; k++) acc[k] += qv * mus2[quarter*64 + c][k];
    }
    #pragma unroll
    for (int k = 0; k < K; k++) zpart[quarter][token][k] = acc[k];
    __syncthreads();
    if (tid < CHT) {
        float s[K];
        #pragma unroll
        for (int k = 0; k < K; k++)
            s[k] = (zpart[0][tid][k] + zpart[1][tid][k]) +
                   (zpart[2][tid][k] + zpart[3][tid][k]);
        float m = s[0];
        #pragma unroll
        for (int k = 1; k < K; k++) m = fmaxf(m, s[k]);
        float sum = 0.f;
        #pragma unroll
        for (int k = 0; k < K; k++) { s[k] = __expf(s[k] - m); sum += s[k]; }
        float inv = 1.f / sum;
        #pragma unroll
        for (int k = 0; k < K; k++) P[(size_t)(b*NN + n) * K + k] = s[k] * inv;
    }
}

// ---------------- PMMS-2: node = mu1 (b,256,5), 10 iterations fully in-block ----------------
__global__ __launch_bounds__(256) void pmms2_kernel(const float* __restrict__ mu1,
                                                    const float* __restrict__ mu_b,
                                                    float* __restrict__ mu2) {
    const int b = blockIdx.x, c = threadIdx.x;
    __shared__ float node[256][5];
    __shared__ float zsh[5][2];
    __shared__ float Ssh[10];
    __shared__ float red[8];
    #pragma unroll
    for (int n = 0; n < 5; n++) node[c][n] = mu1[(b*256 + c) * 5 + n];
    float mk0 = mu_b[c*2 + 0], mk1 = mu_b[c*2 + 1];

    for (int it = 0; it < 10; it++) {
        #pragma unroll
        for (int j = 0; j < 10; j++) {
            int n = j >> 1, k = j & 1;
            float v = node[c][n] * (k ? mk1 : mk0);
            float s = blockReduceSum256(v, red);
            if (c == 0) Ssh[j] = s;
        }
        __syncthreads();
        if (c == 0) {
            float csum0 = 0.f, csum1 = 0.f;
            float zt[5][2];
            #pragma unroll
            for (int n = 0; n < 5; n++) {
                float a = 20.f * Ssh[n*2 + 0];
                float q = 20.f * Ssh[n*2 + 1];
                float m = fmaxf(a, q);
                float ea = __expf(a - m), eb = __expf(q - m);
                float inv = 1.f / (ea + eb);
                zt[n][0] = ea * inv; zt[n][1] = eb * inv;
                csum0 += zt[n][0];   csum1 += zt[n][1];
            }
            #pragma unroll
            for (int n = 0; n < 5; n++) {
                zsh[n][0] = zt[n][0] / (1e-6f + csum0);
                zsh[n][1] = zt[n][1] / (1e-6f + csum1);
            }
        }
        __syncthreads();
        float nk0 = 0.f, nk1 = 0.f;
        #pragma unroll
        for (int n = 0; n < 5; n++) {
            nk0 += node[c][n] * zsh[n][0];
            nk1 += node[c][n] * zsh[n][1];
        }
        float s0 = blockReduceSum256(nk0 * nk0, red);
        float s1 = blockReduceSum256(nk1 * nk1, red);
        mk0 = nk0 / (1e-6f + sqrtf(s0));
        mk1 = nk1 / (1e-6f + sqrtf(s1));
        __syncthreads();
    }
    mu2[(b*256 + c) * 2 + 0] = mk0;
    mu2[(b*256 + c) * 2 + 1] = mk1;
}

// ---------------- node_weight: conv(1->16)+BN+ReLU+conv(16->1)+sigmoid gating ----------------
__global__ __launch_bounds__(1024) void nw_kernel(const float* __restrict__ P, int CH,
                                                  const float* __restrict__ w1,
                                                  const float* __restrict__ b1,
                                                  const float* __restrict__ g,
                                                  const float* __restrict__ be,
                                                  const float* __restrict__ w2,
                                                  const float* __restrict__ b2,
                                                  float* __restrict__ out, int outOff) {
    __shared__ float img[34][34];
    __shared__ float t1[8][34][34];
    __shared__ float sw1[144], sw2[144], sb1[16], sg[16], sbe[16];
    const int blk = blockIdx.x;
    const int b = blk / CH, ch = blk % CH;
    const int t = threadIdx.x;
    const int r = t >> 5, c = t & 31;

    for (int i = t; i < 34*34; i += 1024) ((float*)img)[i] = 0.f;
    for (int i = t; i < 8*34*34; i += 1024) ((float*)t1)[i] = 0.f;
    const float bninv = rsqrtf(1.f + 1e-5f);
    if (t < 144) { sw1[t] = w1[t]; sw2[t] = w2[t]; }
    if (t < 16)  { sb1[t] = b1[t]; sg[t] = g[t] * bninv; sbe[t] = be[t]; }
    __syncthreads();

    const int n = r * 32 + c;
    float xv = P[(size_t)((b << 10) + n) * CH + ch];
    img[r + 1][c + 1] = xv;
    float acc = b2[0];

    for (int half = 0; half < 2; half++) {
        __syncthreads();
        #pragma unroll
        for (int oc = 0; oc < 8; oc++) {
            int o = half * 8 + oc;
            float v = sb1[o];
            #pragma unroll
            for (int dy = 0; dy < 3; dy++)
                #pragma unroll
                for (int dx = 0; dx < 3; dx++)
                    v += sw1[o*9 + dy*3 + dx] * img[r + dy][c + dx];
            v = fmaxf(v * sg[o] + sbe[o], 0.f);
            t1[oc][r + 1][c + 1] = v;
        }
        __syncthreads();
        #pragma unroll
        for (int ic = 0; ic < 8; ic++) {
            int i2 = half * 8 + ic;
            #pragma unroll
            for (int dy = 0; dy < 3; dy++)
                #pragma unroll
                for (int dx = 0; dx < 3; dx++)
                    acc += sw2[i2*9 + dy*3 + dx] * t1[ic][r + dy][c + dx];
        }
    }
    float y = 1.f / (1.f + __expf(-acc));
    out[(size_t)((b << 10) + n) * 8 + outOff + ch] = xv * y;
}

// ---------------- launch ----------------
extern "C" void kernel_launch(void* const* d_in, const int* in_sizes, int n_in,
                              void* d_out, int out_size) {
    const float* query = (const float*)d_in[0];
    const float* key   = (const float*)d_in[1];
    const float* value = (const float*)d_in[2];
    const float* lamda = (const float*)d_in[3];
    const float* W0    = (const float*)d_in[4];
    const float* b0    = (const float*)d_in[5];
    const float* W1    = (const float*)d_in[6];
    const float* b1    = (const float*)d_in[7];
    const float* mu_a  = (const float*)d_in[8];
    const float* mu_b  = (const float*)d_in[9];
    const float* nw1_w1 = (const float*)d_in[10];
    const float* nw1_b1 = (const float*)d_in[11];
    const float* nw1_g  = (const float*)d_in[12];
    const float* nw1_be = (const float*)d_in[13];
    const float* nw1_w2 = (const float*)d_in[14];
    const float* nw1_b2 = (const float*)d_in[15];
    const float* nw2_w1 = (const float*)d_in[16];
    const float* nw2_b1 = (const float*)d_in[17];
    const float* nw2_g  = (const float*)d_in[18];
    const float* nw2_be = (const float*)d_in[19];
    const float* nw2_w2 = (const float*)d_in[20];
    const float* nw2_b2 = (const float*)d_in[21];
    float* out = (float*)d_out;

    float *Qp, *Kp, *qT, *kg, *kgpart, *parth, *mu1, *mu2, *P1, *P2;
    float *colpart, *mupart;
    cudaGetSymbolAddress((void**)&Qp, g_Qp);
    cudaGetSymbolAddress((void**)&Kp, g_Kp);
    cudaGetSymbolAddress((void**)&qT, g_qT);
    cudaGetSymbolAddress((void**)&kg, g_kg);
    cudaGetSymbolAddress((void**)&kgpart, g_kgpart);
    cudaGetSymbolAddress((void**)&parth, g_parth);
    cudaGetSymbolAddress((void**)&mu1, g_mu1);
    cudaGetSymbolAddress((void**)&mu2, g_mu2);
    cudaGetSymbolAddress((void**)&colpart, g_colpart);
    cudaGetSymbolAddress((void**)&mupart, g_mupart);
    cudaGetSymbolAddress((void**)&P1, g_P1);
    cudaGetSymbolAddress((void**)&P2, g_P2);

    float* mp[2] = {mupart, mupart + BB*NCH*5*DD};
    float* cp[2] = {colpart, colpart + BB*NCH*5};

    // Transpose query for coalesced PMMS access
    transpose_kernel<<<dim3(32, 8, 16), dim3(32, 8)>>>(query, qT);

    // Projections (fp16 tensor-core MMA, fp32 accumulate)
    proj_mma16_kernel<<<dim3(2, 128), 256>>>(query, W0, b0, Qp);
    proj_mma16_kernel<<<dim3(2, 128), 256>>>(key,   W1, b1, Kp);

    // Attention
    kg_partial_kernel<<<dim3(8, BB), 256>>>(Kp, value, kgpart);
    kg_finalize_kernel<<<BB, 256>>>(kgpart, kg);
    flash_mma16_kernel<<<dim3(8, NH, BB), 256>>>(Qp, Kp, value, parth);
    combine_kernel<<<64, 256>>>(Qp, kg, parth, lamda, out);

    // PMMS-1 (K=5, 10 fused iterations, ping-pong partials, 8 chunks, 512 threads)
    for (int it = 0; it < 10; it++) {
        int ob = it & 1;
        int ib = ob ^ 1;
        pmms1_iter_kernel<<<dim3(NCH, BB), 512>>>(qT, query, mu_a,
                                                  mp[ib], cp[ib], mp[ob], cp[ob],
                                                  it == 0 ? 1 : 0);
    }
    mustep_finalize<5><<<BB, 256>>>(mp[1], cp[1], mu1);   // iter 9 wrote buffer 1

    // P1 = softmax(query @ mu1)
    zstepT_kernel<5><<<dim3(NCH, BB), 512>>>(qT, mu1, P1);

    // PMMS-2 (node = mu1, K=2)
    pmms2_kernel<<<BB, 256>>>(mu1, mu_b, mu2);
    zstepT_kernel<2><<<dim3(NCH, BB), 512>>>(qT, mu2, P2);

    // node_weight gating
    nw_kernel<<<BB * 5, 1024>>>(P1, 5, nw1_w1, nw1_b1, nw1_g, nw1_be, nw1_w2, nw1_b2, out, 1);
    nw_kernel<<<BB * 2, 1024>>>(P2, 2, nw2_w1, nw2_b1, nw2_g, nw2_be, nw2_w2, nw2_b2, out, 6);
}

// round 17
// speedup vs baseline: 2.9834x; 1.1435x over previous
#include <cuda_runtime.h>
#include <cuda_fp16.h>
#include <cstdint>
#include <math.h>

#define BB 16
#define NN 1024
#define DD 256
#define NH 8
#define DKH 32
#define NCH 8     // PMMS chunks per batch
#define CHT 128   // tokens per chunk
#define NBLK (NCH*BB)   // 128 persistent blocks
#define QS_STRIDE 257
#define ATTN_SCALE 0.17677669529663687f  // 1/sqrt(32)

// ---------------- scratch (static device globals; no allocation) ----------------
__device__ float g_Qp[BB*NN*DD];       // 16 MB
__device__ float g_Kp[BB*NN*DD];       // 16 MB
__device__ float g_kg[BB*DD];
__device__ float g_kgpart[BB*8*DD];
__device__ float g_parth[BB*NH*NN];
__device__ float g_mu2[BB*DD*2];
__device__ float g_colpart[2][BB*NCH*5];
__device__ float g_mupart[2][BB*NCH*5*DD];
__device__ float g_P1[BB*NN*5];
__device__ float g_P2[BB*NN*2];
__device__ unsigned g_bar_ctr;
__device__ unsigned g_bar_exit;

// ---------------- helpers ----------------
// 512-thread block reduction; ALL threads must call (idle lanes pass 0)
__device__ __forceinline__ float blockReduceSum512(float v, float* red) {
    #pragma unroll
    for (int off = 16; off; off >>= 1) v += __shfl_down_sync(0xffffffffu, v, off);
    int w = threadIdx.x >> 5;
    if ((threadIdx.x & 31) == 0) red[w] = v;
    __syncthreads();
    if (threadIdx.x < 32) {
        float r = (threadIdx.x < 16) ? red[threadIdx.x] : 0.f;
        #pragma unroll
        for (int off = 8; off; off >>= 1) r += __shfl_down_sync(0xffffffffu, r, off);
        if (threadIdx.x == 0) red[0] = r;
    }
    __syncthreads();
    float out = red[0];
    __syncthreads();
    return out;
}

__device__ __forceinline__ void grid_barrier(int gen) {
    __syncthreads();
    if (threadIdx.x == 0) {
        __threadfence();
        atomicAdd(&g_bar_ctr, 1u);
        const unsigned target = (unsigned)gen * NBLK;
        volatile unsigned* vp = &g_bar_ctr;
        while (*vp < target) { __nanosleep(64); }
        __threadfence();
    }
    __syncthreads();
}

__device__ __forceinline__ uint32_t pack_h2(float a, float b) {
    __half2 h = __floats2half2_rn(a, b);
    return *(uint32_t*)&h;
}

__device__ __forceinline__ void mma_f16(float& c0, float& c1, float& c2, float& c3,
                                        uint32_t a0, uint32_t a1, uint32_t a2, uint32_t a3,
                                        uint32_t b0, uint32_t b1) {
    asm("mma.sync.aligned.m16n8k16.row.col.f32.f16.f16.f32 "
        "{%0,%1,%2,%3}, {%4,%5,%6,%7}, {%8,%9}, {%0,%1,%2,%3};"
        : "+f"(c0), "+f"(c1), "+f"(c2), "+f"(c3)
        : "r"(a0), "r"(a1), "r"(a2), "r"(a3), "r"(b0), "r"(b1));
}

// ---------------- FP16 MMA projection GEMM: C[16384,256] = A @ W^T + bias ----------------
__global__ __launch_bounds__(256) void proj_mma16_kernel(const float* __restrict__ A,
                                                         const float* __restrict__ W,
                                                         const float* __restrict__ bias,
                                                         float* __restrict__ C) {
    __shared__ uint32_t As[128][20];   // 16 half2 per row (+4 pad)
    __shared__ uint32_t Ws[128][20];
    const int bm = blockIdx.y * 128;
    const int bn = blockIdx.x * 128;
    const int tid = threadIdx.x;
    const int wid = tid >> 5, lane = tid & 31;
    const int wm = wid & 3, wn = wid >> 2;
    const int gid = lane >> 2, tig = lane & 3;

    float acc[2][8][4];
    #pragma unroll
    for (int mt = 0; mt < 2; mt++)
        #pragma unroll
        for (int nt = 0; nt < 8; nt++)
            #pragma unroll
            for (int i = 0; i < 4; i++) acc[mt][nt][i] = 0.f;

    for (int k0 = 0; k0 < 256; k0 += 32) {
        __syncthreads();
        #pragma unroll
        for (int i = tid; i < 128*16; i += 256) {
            int r = i >> 4, c2 = i & 15;
            float2 a = *(const float2*)&A[(size_t)(bm + r) * 256 + k0 + c2*2];
            float2 w = *(const float2*)&W[(size_t)(bn + r) * 256 + k0 + c2*2];
            As[r][c2] = pack_h2(a.x, a.y);
            Ws[r][c2] = pack_h2(w.x, w.y);
        }
        __syncthreads();
        #pragma unroll
        for (int ks = 0; ks < 2; ks++) {
            uint32_t afr[2][4];
            #pragma unroll
            for (int mt = 0; mt < 2; mt++) {
                int r = wm*32 + mt*16 + gid;
                int h2 = ks*8 + tig;
                afr[mt][0] = As[r][h2];       afr[mt][1] = As[r+8][h2];
                afr[mt][2] = As[r][h2 + 4];   afr[mt][3] = As[r+8][h2 + 4];
            }
            #pragma unroll
            for (int nt = 0; nt < 8; nt++) {
                int nr = wn*64 + nt*8 + gid;
                uint32_t b0 = Ws[nr][ks*8 + tig];
                uint32_t b1 = Ws[nr][ks*8 + tig + 4];
                #pragma unroll
                for (int mt = 0; mt < 2; mt++)
                    mma_f16(acc[mt][nt][0], acc[mt][nt][1], acc[mt][nt][2], acc[mt][nt][3],
                            afr[mt][0], afr[mt][1], afr[mt][2], afr[mt][3], b0, b1);
            }
        }
    }
    #pragma unroll
    for (int mt = 0; mt < 2; mt++) {
        int r = bm + wm*32 + mt*16 + gid;
        #pragma unroll
        for (int nt = 0; nt < 8; nt++) {
            int col = bn + wn*64 + nt*8 + 2*tig;
            float bv0 = bias[col], bv1 = bias[col + 1];
            float2 v0 = make_float2(acc[mt][nt][0] + bv0, acc[mt][nt][1] + bv1);
            float2 v1 = make_float2(acc[mt][nt][2] + bv0, acc[mt][nt][3] + bv1);
            *(float2*)&C[(size_t)r * 256 + col] = v0;
            *(float2*)&C[(size_t)(r + 8) * 256 + col] = v1;
        }
    }
}

// ---------------- key_global partials ----------------
__global__ __launch_bounds__(256) void kg_partial_kernel(const float* __restrict__ Kp,
                                                         const float* __restrict__ value,
                                                         float* __restrict__ kgpart) {
    __shared__ float vs[128];
    const int chunk = blockIdx.x, b = blockIdx.y;
    const int c = threadIdx.x;
    const int n0 = chunk * 128;
    if (c < 128) vs[c] = value[b*NN + n0 + c];
    __syncthreads();
    const float* kp = &Kp[(size_t)(b*NN + n0) * DD + c];
    float a0 = 0.f, a1 = 0.f, a2 = 0.f, a3 = 0.f;
    #pragma unroll 4
    for (int n = 0; n < 128; n += 4) {
        a0 += kp[(size_t)(n+0) * DD] * vs[n+0];
        a1 += kp[(size_t)(n+1) * DD] * vs[n+1];
        a2 += kp[(size_t)(n+2) * DD] * vs[n+2];
        a3 += kp[(size_t)(n+3) * DD] * vs[n+3];
    }
    kgpart[(size_t)(b*8 + chunk) * DD + c] = (a0 + a1) + (a2 + a3);
}

__global__ __launch_bounds__(256) void kg_finalize_kernel(const float* __restrict__ kgpart,
                                                          float* __restrict__ kg) {
    const int b = blockIdx.x, c = threadIdx.x;
    float s = 0.f;
    #pragma unroll
    for (int ch = 0; ch < 8; ch++) s += kgpart[(size_t)(b*8 + ch) * DD + c];
    kg[b*DD + c] = s * (1.0f / NN);
}

// ---------------- FP16 m16n8k16 flash attention with scalar V ----------------
__global__ __launch_bounds__(256) void flash_mma16_kernel(const float* __restrict__ Qp,
                                                          const float* __restrict__ Kp,
                                                          const float* __restrict__ value,
                                                          float* __restrict__ parth) {
    __shared__ uint32_t Qs[128][20];   // 16 half2 per row (+4 pad)
    __shared__ uint32_t Ks[128][20];
    __shared__ float vs[128];
    __shared__ float lred[2][128];
    __shared__ float sred[2][128];
    const int b = blockIdx.z, h = blockIdx.y;
    const int q0 = blockIdx.x * 128;
    const int tid = threadIdx.x;
    const int wid = tid >> 5, lane = tid & 31;
    const int wm = wid & 3, wn = wid >> 2;
    const int gid = lane >> 2, tig = lane & 3;

    {
        const float* src = &Qp[(size_t)(b*NN + q0) * DD + h * DKH];
        #pragma unroll
        for (int i = tid; i < 128*16; i += 256) {
            int r = i >> 4, c2 = i & 15;
            float2 v = *(const float2*)&src[(size_t)r * DD + c2*2];
            Qs[r][c2] = pack_h2(v.x, v.y);
        }
    }
    __syncthreads();

    uint32_t afr[2][2][4];
    #pragma unroll
    for (int mt = 0; mt < 2; mt++)
        #pragma unroll
        for (int ks = 0; ks < 2; ks++) {
            int r = wm*32 + mt*16 + gid;
            int h2 = ks*8 + tig;
            afr[mt][ks][0] = Qs[r][h2];       afr[mt][ks][1] = Qs[r+8][h2];
            afr[mt][ks][2] = Qs[r][h2 + 4];   afr[mt][ks][3] = Qs[r+8][h2 + 4];
        }

    float la[2][2] = {{0.f,0.f},{0.f,0.f}};
    float sa[2][2] = {{0.f,0.f},{0.f,0.f}};

    for (int kt = 0; kt < NN; kt += 128) {
        __syncthreads();
        const float* ksrc = &Kp[(size_t)(b*NN + kt) * DD + h * DKH];
        #pragma unroll
        for (int i = tid; i < 128*16; i += 256) {
            int r = i >> 4, c2 = i & 15;
            float2 v = *(const float2*)&ksrc[(size_t)r * DD + c2*2];
            Ks[r][c2] = pack_h2(v.x, v.y);
        }
        if (tid < 128) vs[tid] = value[b*NN + kt + tid];
        __syncthreads();

        #pragma unroll
        for (int nt = 0; nt < 8; nt++) {
            int nb = wn*64 + nt*8;
            uint32_t bfr[2][2];
            #pragma unroll
            for (int ks = 0; ks < 2; ks++) {
                bfr[ks][0] = Ks[nb + gid][ks*8 + tig];
                bfr[ks][1] = Ks[nb + gid][ks*8 + tig + 4];
            }
            float v0 = vs[nb + 2*tig], v1 = vs[nb + 2*tig + 1];
            #pragma unroll
            for (int mt = 0; mt < 2; mt++) {
                float c0 = 0.f, c1 = 0.f, c2 = 0.f, c3 = 0.f;
                #pragma unroll
                for (int ks = 0; ks < 2; ks++)
                    mma_f16(c0, c1, c2, c3,
                            afr[mt][ks][0], afr[mt][ks][1], afr[mt][ks][2], afr[mt][ks][3],
                            bfr[ks][0], bfr[ks][1]);
                float e0 = __expf(c0 * ATTN_SCALE);
                float e1 = __expf(c1 * ATTN_SCALE);
                float e2 = __expf(c2 * ATTN_SCALE);
                float e3 = __expf(c3 * ATTN_SCALE);
                la[mt][0] += e0 + e1;  sa[mt][0] += e0*v0 + e1*v1;
                la[mt][1] += e2 + e3;  sa[mt][1] += e2*v0 + e3*v1;
            }
        }
    }

    #pragma unroll
    for (int mt = 0; mt < 2; mt++)
        #pragma unroll
        for (int rr = 0; rr < 2; rr++) {
            float l = la[mt][rr], s = sa[mt][rr];
            l += __shfl_xor_sync(0xffffffffu, l, 1);
            l += __shfl_xor_sync(0xffffffffu, l, 2);
            s += __shfl_xor_sync(0xffffffffu, s, 1);
            s += __shfl_xor_sync(0xffffffffu, s, 2);
            la[mt][rr] = l; sa[mt][rr] = s;
        }
    if (tig == 0) {
        #pragma unroll
        for (int mt = 0; mt < 2; mt++) {
            int r0 = wm*32 + mt*16 + gid;
            lred[wn][r0]     = la[mt][0];  sred[wn][r0]     = sa[mt][0];
            lred[wn][r0 + 8] = la[mt][1];  sred[wn][r0 + 8] = sa[mt][1];
        }
    }
    __syncthreads();
    if (tid < 128) {
        float l = lred[0][tid] + lred[1][tid];
        float s = sred[0][tid] + sred[1][tid];
        parth[(size_t)(b*NH + h) * NN + q0 + tid] = s / l;
    }
}

// ---------------- combine: f = (1-lam)*part + lam*whole -> out[:, :, 0] ----------------
__global__ __launch_bounds__(256) void combine_kernel(const float* __restrict__ Qp,
                                                      const float* __restrict__ kg,
                                                      const float* __restrict__ parth,
                                                      const float* __restrict__ lamda,
                                                      float* __restrict__ out) {
    int idx = blockIdx.x * 256 + threadIdx.x;   // b*1024+n
    int b = idx >> 10, n = idx & 1023;
    const float4* q   = (const float4*)&Qp[(size_t)idx * DD];
    const float4* kgp = (const float4*)&kg[b * DD];
    float wsum = 0.f;
    #pragma unroll
    for (int h = 0; h < NH; h++) {
        float d = 0.f;
        #pragma unroll
        for (int i = 0; i < 8; i++) {
            float4 qv = q[h*8 + i], kv = kgp[h*8 + i];
            d += qv.x*kv.x + qv.y*kv.y + qv.z*kv.z + qv.w*kv.w;
        }
        wsum += fmaxf(d * ATTN_SCALE, 0.f);
    }
    float whole = wsum * 0.125f;
    float p = 0.f;
    #pragma unroll
    for (int h = 0; h < NH; h++) p += parth[(size_t)(b*NH + h) * NN + n];
    p *= 0.125f;
    float lam = lamda[0];
    out[(size_t)idx * 8] = (1.f - lam) * p + lam * whole;
}

// ---------------- persistent PMMS: 10 iters + P1 + pmms2 + P2, one launch ----------------
__global__ __launch_bounds__(512) void pmms_persistent_kernel(
        const float* __restrict__ query,
        const float* __restrict__ mu_a,
        const float* __restrict__ mu_b,
        float* __restrict__ mupart0, float* __restrict__ colpart0,
        float* __restrict__ mupart1, float* __restrict__ colpart1,
        float* __restrict__ mu2g,
        float* __restrict__ P1, float* __restrict__ P2) {
    extern __shared__ float qs[];          // [CHT][QS_STRIDE]
    __shared__ float mus2[256][8];         // [c][k]
    __shared__ float zpart[4][CHT][6];
    __shared__ float zz[CHT][8];
    __shared__ float bpart[2][256][6];
    __shared__ float red[16];
    __shared__ float mu2s[256][2];
    __shared__ float node[256][5];
    __shared__ float zsh[5][2];
    __shared__ float Ssh[10];

    const int chunk = blockIdx.x & (NCH - 1);
    const int b = blockIdx.x >> 3;
    const int tid = threadIdx.x;

    // ---- load this chunk's query tile into smem (once) ----
    {
        const float4* qsrc = (const float4*)&query[(size_t)(b*NN + chunk*CHT) * DD];
        #pragma unroll 4
        for (int i = tid; i < CHT * 64; i += 512) {
            int r = i >> 6, c4 = i & 63;
            float4 v = qsrc[(size_t)r * 64 + c4];
            float* dst = &qs[r * QS_STRIDE + c4 * 4];
            dst[0] = v.x; dst[1] = v.y; dst[2] = v.z; dst[3] = v.w;
        }
    }
    __syncthreads();

    int gen = 0;
    for (int it = 0; it < 10; it++) {
        const float* mupart_in  = (it & 1) ? mupart0 : mupart1;
        const float* colpart_in = (it & 1) ? colpart0 : colpart1;
        float* mupart_out  = (it & 1) ? mupart1 : mupart0;
        float* colpart_out = (it & 1) ? colpart1 : colpart0;

        // ---- Phase 0: materialize current mu into mus2 ----
        if (it == 0) {
            for (int i = tid; i < 256 * 5; i += 512) mus2[i / 5][i % 5] = mu_a[i];
            __syncthreads();
        } else {
            float v[5] = {0.f, 0.f, 0.f, 0.f, 0.f};
            if (tid < 256) {
                const int c = tid;
                #pragma unroll
                for (int k = 0; k < 5; k++) {
                    float cs = 0.f, a = 0.f;
                    #pragma unroll
                    for (int ch = 0; ch < NCH; ch++) {
                        cs += colpart_in[(b*NCH + ch) * 5 + k];
                        a  += mupart_in[(size_t)((b*NCH + ch) * 5 + k) * 256 + c];
                    }
                    v[k] = a / (1e-6f + cs);
                }
            }
            #pragma unroll
            for (int k = 0; k < 5; k++) {
                float s = blockReduceSum512(v[k] * v[k], red);
                if (tid < 256) mus2[tid][k] = v[k] / (1e-6f + sqrtf(s));
            }
            __syncthreads();
        }

        // ---- Phase A: z (kappa=20), 4-way channel split from smem q ----
        {
            const int token = tid & (CHT - 1);
            const int quarter = tid >> 7;
            const float* qrow = &qs[token * QS_STRIDE + quarter * 64];
            float acc[5] = {0.f, 0.f, 0.f, 0.f, 0.f};
            #pragma unroll 8
            for (int c = 0; c < 64; c++) {
                float qv = qrow[c];
                float4 m4 = *(const float4*)&mus2[quarter*64 + c][0];
                float m5 = mus2[quarter*64 + c][4];
                acc[0] += qv * m4.x; acc[1] += qv * m4.y; acc[2] += qv * m4.z;
                acc[3] += qv * m4.w; acc[4] += qv * m5;
            }
            #pragma unroll
            for (int k = 0; k < 5; k++) zpart[quarter][token][k] = acc[k];
            __syncthreads();

            float z[5] = {0.f, 0.f, 0.f, 0.f, 0.f};
            if (tid < CHT) {
                float s[5];
                #pragma unroll
                for (int k = 0; k < 5; k++)
                    s[k] = (zpart[0][tid][k] + zpart[1][tid][k]) +
                           (zpart[2][tid][k] + zpart[3][tid][k]);
                float m = s[0];
                #pragma unroll
                for (int k = 1; k < 5; k++) m = fmaxf(m, s[k]);
                float sum = 0.f;
                #pragma unroll
                for (int k = 0; k < 5; k++) { z[k] = __expf(20.f * (s[k] - m)); sum += z[k]; }
                float inv = 1.f / sum;
                #pragma unroll
                for (int k = 0; k < 5; k++) { z[k] *= inv; zz[tid][k] = z[k]; }
            }
            #pragma unroll
            for (int k = 0; k < 5; k++) {
                float s = blockReduceSum512(z[k], red);
                if (tid == 0) colpart_out[(b*NCH + chunk) * 5 + k] = s;
            }
        }

        // ---- Phase B: mu partials, 2-way token split from smem q ----
        {
            const int c = tid & 255;
            const int th = tid >> 8;
            float acc[5] = {0.f, 0.f, 0.f, 0.f, 0.f};
            #pragma unroll 8
            for (int n = 0; n < 64; n++) {
                float qv = qs[(th*64 + n) * QS_STRIDE + c];
                float4 z4 = *(const float4*)&zz[th*64 + n][0];
                float z5 = zz[th*64 + n][4];
                acc[0] += qv * z4.x; acc[1] += qv * z4.y; acc[2] += qv * z4.z;
                acc[3] += qv * z4.w; acc[4] += qv * z5;
            }
            #pragma unroll
            for (int k = 0; k < 5; k++) bpart[th][c][k] = acc[k];
            __syncthreads();
            if (tid < 256) {
                #pragma unroll
                for (int k = 0; k < 5; k++)
                    mupart_out[(size_t)((b*NCH + chunk) * 5 + k) * 256 + tid] =
                        bpart[0][tid][k] + bpart[1][tid][k];
            }
        }
        grid_barrier(++gen);
    }

    // ---- final mu1 finalize (iter 9 wrote buffer 1) ----
    {
        float v[5] = {0.f, 0.f, 0.f, 0.f, 0.f};
        if (tid < 256) {
            const int c = tid;
            #pragma unroll
            for (int k = 0; k < 5; k++) {
                float cs = 0.f, a = 0.f;
                #pragma unroll
                for (int ch = 0; ch < NCH; ch++) {
                    cs += colpart1[(b*NCH + ch) * 5 + k];
                    a  += mupart1[(size_t)((b*NCH + ch) * 5 + k) * 256 + c];
                }
                v[k] = a / (1e-6f + cs);
            }
        }
        #pragma unroll
        for (int k = 0; k < 5; k++) {
            float s = blockReduceSum512(v[k] * v[k], red);
            if (tid < 256) mus2[tid][k] = v[k] / (1e-6f + sqrtf(s));
        }
        __syncthreads();
    }

    // ---- P1 = softmax(q @ mu1), kappa=1, from smem q ----
    {
        const int token = tid & (CHT - 1);
        const int quarter = tid >> 7;
        const float* qrow = &qs[token * QS_STRIDE + quarter * 64];
        float acc[5] = {0.f, 0.f, 0.f, 0.f, 0.f};
        #pragma unroll 8
        for (int c = 0; c < 64; c++) {
            float qv = qrow[c];
            float4 m4 = *(const float4*)&mus2[quarter*64 + c][0];
            float m5 = mus2[quarter*64 + c][4];
            acc[0] += qv * m4.x; acc[1] += qv * m4.y; acc[2] += qv * m4.z;
            acc[3] += qv * m4.w; acc[4] += qv * m5;
        }
        #pragma unroll
        for (int k = 0; k < 5; k++) zpart[quarter][token][k] = acc[k];
        __syncthreads();
        if (tid < CHT) {
            const int n = chunk * CHT + tid;
            float s[5];
            #pragma unroll
            for (int k = 0; k < 5; k++)
                s[k] = (zpart[0][tid][k] + zpart[1][tid][k]) +
                       (zpart[2][tid][k] + zpart[3][tid][k]);
            float m = s[0];
            #pragma unroll
            for (int k = 1; k < 5; k++) m = fmaxf(m, s[k]);
            float sum = 0.f;
            #pragma unroll
            for (int k = 0; k < 5; k++) { s[k] = __expf(s[k] - m); sum += s[k]; }
            float inv = 1.f / sum;
            #pragma unroll
            for (int k = 0; k < 5; k++) P1[(size_t)(b*NN + n) * 5 + k] = s[k] * inv;
        }
        __syncthreads();
    }

    // ---- pmms2 on chunk-0 blocks (mu1 is in mus2); 512-wide reductions ----
    if (chunk == 0) {
        float mk0 = 0.f, mk1 = 0.f;
        if (tid < 256) {
            #pragma unroll
            for (int n = 0; n < 5; n++) node[tid][n] = mus2[tid][n];
            mk0 = mu_b[tid*2 + 0];
            mk1 = mu_b[tid*2 + 1];
        }
        __syncthreads();
        for (int it2 = 0; it2 < 10; it2++) {
            #pragma unroll
            for (int j = 0; j < 10; j++) {
                int n = j >> 1, k = j & 1;
                float v = (tid < 256) ? node[tid][n] * (k ? mk1 : mk0) : 0.f;
                float s = blockReduceSum512(v, red);
                if (tid == 0) Ssh[j] = s;
            }
            __syncthreads();
            if (tid == 0) {
                float csum0 = 0.f, csum1 = 0.f;
                float zt[5][2];
                #pragma unroll
                for (int n = 0; n < 5; n++) {
                    float a = 20.f * Ssh[n*2 + 0];
                    float q = 20.f * Ssh[n*2 + 1];
                    float m = fmaxf(a, q);
                    float ea = __expf(a - m), eb = __expf(q - m);
                    float inv = 1.f / (ea + eb);
                    zt[n][0] = ea * inv; zt[n][1] = eb * inv;
                    csum0 += zt[n][0];   csum1 += zt[n][1];
                }
                #pragma unroll
                for (int n = 0; n < 5; n++) {
                    zsh[n][0] = zt[n][0] / (1e-6f + csum0);
                    zsh[n][1] = zt[n][1] / (1e-6f + csum1);
                }
            }
            __syncthreads();
            float nk0 = 0.f, nk1 = 0.f;
            if (tid < 256) {
                #pragma unroll
                for (int n = 0; n < 5; n++) {
                    nk0 += node[tid][n] * zsh[n][0];
                    nk1 += node[tid][n] * zsh[n][1];
                }
            }
            float s0 = blockReduceSum512(nk0 * nk0, red);
            float s1 = blockReduceSum512(nk1 * nk1, red);
            mk0 = nk0 / (1e-6f + sqrtf(s0));
            mk1 = nk1 / (1e-6f + sqrtf(s1));
            __syncthreads();
        }
        if (tid < 256) {
            mu2g[(b*256 + tid) * 2 + 0] = mk0;
            mu2g[(b*256 + tid) * 2 + 1] = mk1;
        }
    }
    grid_barrier(++gen);

    // ---- P2 = softmax(q @ mu2), kappa=1 ----
    {
        if (tid < 256) {
            mu2s[tid][0] = mu2g[(b*256 + tid) * 2 + 0];
            mu2s[tid][1] = mu2g[(b*256 + tid) * 2 + 1];
        }
        __syncthreads();
        const int token = tid & (CHT - 1);
        const int quarter = tid >> 7;
        const float* qrow = &qs[token * QS_STRIDE + quarter * 64];
        float a0 = 0.f, a1 = 0.f;
        #pragma unroll 8
        for (int c = 0; c < 64; c++) {
            float qv = qrow[c];
            a0 += qv * mu2s[quarter*64 + c][0];
            a1 += qv * mu2s[quarter*64 + c][1];
        }
        zpart[quarter][token][0] = a0;
        zpart[quarter][token][1] = a1;
        __syncthreads();
        if (tid < CHT) {
            const int n = chunk * CHT + tid;
            float s0 = (zpart[0][tid][0] + zpart[1][tid][0]) +
                       (zpart[2][tid][0] + zpart[3][tid][0]);
            float s1 = (zpart[0][tid][1] + zpart[1][tid][1]) +
                       (zpart[2][tid][1] + zpart[3][tid][1]);
            float m = fmaxf(s0, s1);
            float e0 = __expf(s0 - m), e1 = __expf(s1 - m);
            float inv = 1.f / (e0 + e1);
            P2[(size_t)(b*NN + n) * 2 + 0] = e0 * inv;
            P2[(size_t)(b*NN + n) * 2 + 1] = e1 * inv;
        }
    }

    // ---- reset barrier counters for next graph replay ----
    __syncthreads();
    if (tid == 0) {
        unsigned r = atomicAdd(&g_bar_exit, 1u);
        if (r == NBLK - 1) {
            g_bar_ctr = 0u;
            g_bar_exit = 0u;
            __threadfence();
        }
    }
}

// ---------------- node_weight: conv(1->16)+BN+ReLU+conv(16->1)+sigmoid gating ----------------
__global__ __launch_bounds__(1024) void nw_kernel(const float* __restrict__ P, int CH,
                                                  const float* __restrict__ w1,
                                                  const float* __restrict__ b1,
                                                  const float* __restrict__ g,
                                                  const float* __restrict__ be,
                                                  const float* __restrict__ w2,
                                                  const float* __restrict__ b2,
                                                  float* __restrict__ out, int outOff) {
    __shared__ float img[34][34];
    __shared__ float t1[8][34][34];
    __shared__ float sw1[144], sw2[144], sb1[16], sg[16], sbe[16];
    const int blk = blockIdx.x;
    const int b = blk / CH, ch = blk % CH;
    const int t = threadIdx.x;
    const int r = t >> 5, c = t & 31;

    for (int i = t; i < 34*34; i += 1024) ((float*)img)[i] = 0.f;
    for (int i = t; i < 8*34*34; i += 1024) ((float*)t1)[i] = 0.f;
    const float bninv = rsqrtf(1.f + 1e-5f);
    if (t < 144) { sw1[t] = w1[t]; sw2[t] = w2[t]; }
    if (t < 16)  { sb1[t] = b1[t]; sg[t] = g[t] * bninv; sbe[t] = be[t]; }
    __syncthreads();

    const int n = r * 32 + c;
    float xv = P[(size_t)((b << 10) + n) * CH + ch];
    img[r + 1][c + 1] = xv;
    float acc = b2[0];

    for (int half = 0; half < 2; half++) {
        __syncthreads();
        #pragma unroll
        for (int oc = 0; oc < 8; oc++) {
            int o = half * 8 + oc;
            float v = sb1[o];
            #pragma unroll
            for (int dy = 0; dy < 3; dy++)
                #pragma unroll
                for (int dx = 0; dx < 3; dx++)
                    v += sw1[o*9 + dy*3 + dx] * img[r + dy][c + dx];
            v = fmaxf(v * sg[o] + sbe[o], 0.f);
            t1[oc][r + 1][c + 1] = v;
        }
        __syncthreads();
        #pragma unroll
        for (int ic = 0; ic < 8; ic++) {
            int i2 = half * 8 + ic;
            #pragma unroll
            for (int dy = 0; dy < 3; dy++)
                #pragma unroll
                for (int dx = 0; dx < 3; dx++)
                    acc += sw2[i2*9 + dy*3 + dx] * t1[ic][r + dy][c + dx];
        }
    }
    float y = 1.f / (1.f + __expf(-acc));
    out[(size_t)((b << 10) + n) * 8 + outOff + ch] = xv * y;
}

// ---------------- launch ----------------
extern "C" void kernel_launch(void* const* d_in, const int* in_sizes, int n_in,
                              void* d_out, int out_size) {
    const float* query = (const float*)d_in[0];
    const float* key   = (const float*)d_in[1];
    const float* value = (const float*)d_in[2];
    const float* lamda = (const float*)d_in[3];
    const float* W0    = (const float*)d_in[4];
    const float* b0    = (const float*)d_in[5];
    const float* W1    = (const float*)d_in[6];
    const float* b1    = (const float*)d_in[7];
    const float* mu_a  = (const float*)d_in[8];
    const float* mu_b  = (const float*)d_in[9];
    const float* nw1_w1 = (const float*)d_in[10];
    const float* nw1_b1 = (const float*)d_in[11];
    const float* nw1_g  = (const float*)d_in[12];
    const float* nw1_be = (const float*)d_in[13];
    const float* nw1_w2 = (const float*)d_in[14];
    const float* nw1_b2 = (const float*)d_in[15];
    const float* nw2_w1 = (const float*)d_in[16];
    const float* nw2_b1 = (const float*)d_in[17];
    const float* nw2_g  = (const float*)d_in[18];
    const float* nw2_be = (const float*)d_in[19];
    const float* nw2_w2 = (const float*)d_in[20];
    const float* nw2_b2 = (const float*)d_in[21];
    float* out = (float*)d_out;

    float *Qp, *Kp, *kg, *kgpart, *parth, *mu2, *P1, *P2;
    float *colpart, *mupart;
    cudaGetSymbolAddress((void**)&Qp, g_Qp);
    cudaGetSymbolAddress((void**)&Kp, g_Kp);
    cudaGetSymbolAddress((void**)&kg, g_kg);
    cudaGetSymbolAddress((void**)&kgpart, g_kgpart);
    cudaGetSymbolAddress((void**)&parth, g_parth);
    cudaGetSymbolAddress((void**)&mu2, g_mu2);
    cudaGetSymbolAddress((void**)&colpart, g_colpart);
    cudaGetSymbolAddress((void**)&mupart, g_mupart);
    cudaGetSymbolAddress((void**)&P1, g_P1);
    cudaGetSymbolAddress((void**)&P2, g_P2);

    float* mp0 = mupart;
    float* mp1 = mupart + BB*NCH*5*DD;
    float* cp0 = colpart;
    float* cp1 = colpart + BB*NCH*5;

    // Projections (fp16 tensor-core MMA, fp32 accumulate)
    proj_mma16_kernel<<<dim3(2, 128), 256>>>(query, W0, b0, Qp);
    proj_mma16_kernel<<<dim3(2, 128), 256>>>(key,   W1, b1, Kp);

    // Attention
    kg_partial_kernel<<<dim3(8, BB), 256>>>(Kp, value, kgpart);
    kg_finalize_kernel<<<BB, 256>>>(kgpart, kg);
    flash_mma16_kernel<<<dim3(8, NH, BB), 256>>>(Qp, Kp, value, parth);
    combine_kernel<<<64, 256>>>(Qp, kg, parth, lamda, out);

    // Persistent PMMS: 10 iterations + P1 + pmms2 + P2 in ONE launch
    static const size_t pmms_smem = (size_t)CHT * QS_STRIDE * sizeof(float);
    cudaFuncSetAttribute(pmms_persistent_kernel,
                         cudaFuncAttributeMaxDynamicSharedMemorySize, (int)pmms_smem);
    pmms_persistent_kernel<<<NBLK, 512, pmms_smem>>>(query, mu_a, mu_b,
                                                     mp0, cp0, mp1, cp1,
                                                     mu2, P1, P2);

    // node_weight gating
    nw_kernel<<<BB * 5, 1024>>>(P1, 5, nw1_w1, nw1_b1, nw1_g, nw1_be, nw1_w2, nw1_b2, out, 1);
    nw_kernel<<<BB * 2, 1024>>>(P2, 2, nw2_w1, nw2_b1, nw2_g, nw2_be, nw2_w2, nw2_b2, out, 6);
}